// round 6
// baseline (speedup 1.0000x reference)
#include <cuda_runtime.h>
#include <cstdint>

// Problem constants
#define B_  4
#define H_  12
#define N_  2048
#define D_  64
#define C_  768
#define BHND (B_*H_*N_*D_)

// Scratch (device globals — no allocation allowed)
__device__ float g_q[BHND];
__device__ float g_k[BHND];
__device__ float g_v[BHND];
__device__ float g_att[B_*N_*C_];

__device__ __forceinline__ float to_tf32(float x){
    uint32_t u = __float_as_uint(x);
    asm("cvt.rna.tf32.f32 %0, %0;" : "+r"(u));
    return __uint_as_float(u);
}

// D = A(16x8, row) * B(8x8, col) + D ; tf32 inputs, fp32 accum
__device__ __forceinline__ void mma8(float d[4], const float a[4], float b0, float b1){
    asm volatile(
        "mma.sync.aligned.m16n8k8.row.col.f32.tf32.tf32.f32 "
        "{%0,%1,%2,%3},{%4,%5,%6,%7},{%8,%9},{%0,%1,%2,%3};\n"
        : "+f"(d[0]), "+f"(d[1]), "+f"(d[2]), "+f"(d[3])
        : "r"(__float_as_uint(a[0])), "r"(__float_as_uint(a[1])),
          "r"(__float_as_uint(a[2])), "r"(__float_as_uint(a[3])),
          "r"(__float_as_uint(b0)),   "r"(__float_as_uint(b1)));
}

// ---------------------------------------------------------------------------
// Generic TF32 GEMM:  out = A[M,K] @ W[K,NO] + bias
// mode 0: row-major store to out
// mode 1: QKV scatter into g_q/g_k/g_v as [B,H,N,D]
// CTA tile 128x128, K-step 32, 8 warps (4x2), warp tile 32x64
// ---------------------------------------------------------------------------
__global__ __launch_bounds__(256) void gemm_tf32_kernel(
    const float* __restrict__ A, const float* __restrict__ W,
    const float* __restrict__ bias, float* __restrict__ out,
    int M, int K, int NO, int mode)
{
    __shared__ float sA[128*36];   // [m][k], pad 36 -> conflict-free frag loads
    __shared__ float sB[32*132];   // [k][n], pad 132

    const int tid  = threadIdx.x;
    const int lane = tid & 31;
    const int warp = tid >> 5;
    const int wm   = warp & 3;     // 0..3 -> m offset wm*32
    const int wn   = warp >> 2;    // 0..1 -> n offset wn*64
    const int m0   = blockIdx.y * 128;
    const int n0   = blockIdx.x * 128;

    float acc[2][8][4];
    #pragma unroll
    for (int i = 0; i < 2; i++)
        #pragma unroll
        for (int j = 0; j < 8; j++)
            #pragma unroll
            for (int r = 0; r < 4; r++) acc[i][j][r] = 0.f;

    const int ra = tid >> 3;            // 0..31
    const int ca = (tid & 7) << 2;      // 0..28
    const int rb = tid >> 5;            // 0..7
    const int cb = (tid & 31) << 2;     // 0..124

    for (int k0 = 0; k0 < K; k0 += 32){
        __syncthreads();
        #pragma unroll
        for (int i = 0; i < 4; i++){
            float4 v = *(const float4*)(A + (size_t)(m0 + ra + i*32)*K + k0 + ca);
            float* p = &sA[(ra + i*32)*36 + ca];
            p[0]=to_tf32(v.x); p[1]=to_tf32(v.y); p[2]=to_tf32(v.z); p[3]=to_tf32(v.w);
        }
        #pragma unroll
        for (int i = 0; i < 4; i++){
            float4 v = *(const float4*)(W + (size_t)(k0 + rb + i*8)*NO + n0 + cb);
            float* p = &sB[(rb + i*8)*132 + cb];
            p[0]=to_tf32(v.x); p[1]=to_tf32(v.y); p[2]=to_tf32(v.z); p[3]=to_tf32(v.w);
        }
        __syncthreads();

        #pragma unroll
        for (int kk = 0; kk < 4; kk++){
            float af[2][4];
            #pragma unroll
            for (int mf = 0; mf < 2; mf++){
                int rbase = wm*32 + mf*16 + (lane>>2);
                int cbase = kk*8 + (lane&3);
                af[mf][0] = sA[rbase*36 + cbase];
                af[mf][1] = sA[(rbase+8)*36 + cbase];
                af[mf][2] = sA[rbase*36 + cbase + 4];
                af[mf][3] = sA[(rbase+8)*36 + cbase + 4];
            }
            #pragma unroll
            for (int nf = 0; nf < 8; nf++){
                int cc = wn*64 + nf*8 + (lane>>2);
                int rr = kk*8 + (lane&3);
                float b0 = sB[rr*132 + cc];
                float b1 = sB[(rr+4)*132 + cc];
                mma8(acc[0][nf], af[0], b0, b1);
                mma8(acc[1][nf], af[1], b0, b1);
            }
        }
    }

    // epilogue
    #pragma unroll
    for (int mf = 0; mf < 2; mf++){
        #pragma unroll
        for (int nf = 0; nf < 8; nf++){
            #pragma unroll
            for (int rr = 0; rr < 2; rr++){
                int gm  = m0 + wm*32 + mf*16 + (lane>>2) + rr*8;
                int gn0 = n0 + wn*64 + nf*8 + 2*(lane&3);
                float v0 = acc[mf][nf][rr*2+0] + bias[gn0];
                float v1 = acc[mf][nf][rr*2+1] + bias[gn0+1];
                if (mode == 0){
                    *(float2*)(out + (size_t)gm*NO + gn0) = make_float2(v0, v1);
                } else {
                    int three = gn0 / 768;
                    int rem   = gn0 % 768;
                    int h     = rem / 64;
                    int d     = rem & 63;        // even, so d+1 stays in same head
                    int b     = gm >> 11;        // /2048
                    int n     = gm & 2047;
                    float* base = (three == 0) ? g_q : (three == 1) ? g_k : g_v;
                    size_t idx = ((size_t)(b*H_ + h)*N_ + n)*D_ + d;
                    *(float2*)(base + idx) = make_float2(v0, v1);
                }
            }
        }
    }
}

// ---------------------------------------------------------------------------
// Fused attention: 128 q-rows per CTA, 8 warps x 16 rows (softmax row stats
// never cross warps). Key tile = 64. alibi streamed gmem->regs, mask (int32!)
// via ballot bitmask, P relayout through warp-private padded smem.
// ---------------------------------------------------------------------------
__global__ __launch_bounds__(256) void attn_kernel(
    const float* __restrict__ alibi, const int* __restrict__ pmask)
{
    extern __shared__ float sm[];
    float* Ks = sm;                 // 64*68
    float* Vs = sm + 64*68;         // 64*68
    float* Ps = sm + 2*64*68;       // 8 warps * 16*68

    const int tid  = threadIdx.x;
    const int lane = tid & 31;
    const int warp = tid >> 5;
    const int q0 = blockIdx.x * 128;
    const int h  = blockIdx.y;
    const int b  = blockIdx.z;
    const float scale = 0.125f;     // D^-0.5, D=64

    const int r0 = q0 + warp*16 + (lane>>2);      // first accum row of this lane
    const float* qp = g_q + (size_t)(b*H_ + h)*N_*D_;

    // Load Q fragments once (pre-scaled, tf32)
    float qa[8][4];
    #pragma unroll
    for (int ks = 0; ks < 8; ks++){
        int c = ks*8 + (lane&3);
        qa[ks][0] = to_tf32(qp[(size_t)r0*64 + c]       * scale);
        qa[ks][1] = to_tf32(qp[(size_t)(r0+8)*64 + c]   * scale);
        qa[ks][2] = to_tf32(qp[(size_t)r0*64 + c+4]     * scale);
        qa[ks][3] = to_tf32(qp[(size_t)(r0+8)*64 + c+4] * scale);
    }

    float o[8][4];
    #pragma unroll
    for (int nf = 0; nf < 8; nf++){ o[nf][0]=o[nf][1]=o[nf][2]=o[nf][3]=0.f; }
    float mrun0 = -1e30f, mrun1 = -1e30f, l0 = 0.f, l1 = 0.f;

    const float* kbase = g_k + (size_t)(b*H_ + h)*N_*D_;
    const float* vbase = g_v + (size_t)(b*H_ + h)*N_*D_;
    const int* pm = pmask + b*N_;           // padding mask stored as int32
    float* Pw = Ps + warp*(16*68);

    for (int j0 = 0; j0 < N_; j0 += 64){
        __syncthreads();
        #pragma unroll
        for (int i = 0; i < 4; i++){
            int idx = tid + i*256;
            int row = idx >> 4;
            int c4  = (idx & 15) << 2;
            float4 kv = *(const float4*)(kbase + (size_t)(j0+row)*64 + c4);
            float* pk = &Ks[row*68 + c4];
            pk[0]=to_tf32(kv.x); pk[1]=to_tf32(kv.y); pk[2]=to_tf32(kv.z); pk[3]=to_tf32(kv.w);
            float4 vv = *(const float4*)(vbase + (size_t)(j0+row)*64 + c4);
            float* pv = &Vs[row*68 + c4];
            pv[0]=to_tf32(vv.x); pv[1]=to_tf32(vv.y); pv[2]=to_tf32(vv.z); pv[3]=to_tf32(vv.w);
        }
        __syncthreads();

        unsigned mlo = __ballot_sync(0xffffffffu, pm[j0 + lane]      != 0);
        unsigned mhi = __ballot_sync(0xffffffffu, pm[j0 + 32 + lane] != 0);

        // S = Q @ K^T
        float s[8][4];
        #pragma unroll
        for (int nf = 0; nf < 8; nf++){ s[nf][0]=s[nf][1]=s[nf][2]=s[nf][3]=0.f; }
        #pragma unroll
        for (int ks = 0; ks < 8; ks++){
            #pragma unroll
            for (int nf = 0; nf < 8; nf++){
                int n = nf*8 + (lane>>2);
                int c = ks*8 + (lane&3);
                float b0 = Ks[n*68 + c];
                float b1 = Ks[n*68 + c + 4];
                mma8(s[nf], qa[ks], b0, b1);
            }
        }

        // + alibi, mask
        const float* ab0 = alibi + ((size_t)((b*H_ + h)*N_ + r0))*N_ + j0;
        const float* ab1 = ab0 + (size_t)8*N_;
        #pragma unroll
        for (int nf = 0; nf < 8; nf++){
            int c = nf*8 + 2*(lane&3);
            unsigned bit0 = ((c   < 32) ? (mlo >> c)        : (mhi >> (c-32)))   & 1u;
            unsigned bit1 = ((c+1 < 32) ? (mlo >> (c+1))    : (mhi >> (c+1-32))) & 1u;
            float2 a0 = *(const float2*)(ab0 + c);
            float2 a1 = *(const float2*)(ab1 + c);
            s[nf][0] = bit0 ? -INFINITY : s[nf][0] + a0.x;
            s[nf][1] = bit1 ? -INFINITY : s[nf][1] + a0.y;
            s[nf][2] = bit0 ? -INFINITY : s[nf][2] + a1.x;
            s[nf][3] = bit1 ? -INFINITY : s[nf][3] + a1.y;
        }

        // online softmax (rows live in quads: lanes 4k..4k+3)
        float mx0 = -INFINITY, mx1 = -INFINITY;
        #pragma unroll
        for (int nf = 0; nf < 8; nf++){
            mx0 = fmaxf(mx0, fmaxf(s[nf][0], s[nf][1]));
            mx1 = fmaxf(mx1, fmaxf(s[nf][2], s[nf][3]));
        }
        mx0 = fmaxf(mx0, __shfl_xor_sync(0xffffffffu, mx0, 1));
        mx0 = fmaxf(mx0, __shfl_xor_sync(0xffffffffu, mx0, 2));
        mx1 = fmaxf(mx1, __shfl_xor_sync(0xffffffffu, mx1, 1));
        mx1 = fmaxf(mx1, __shfl_xor_sync(0xffffffffu, mx1, 2));
        float mn0 = fmaxf(mrun0, mx0);           // mrun >= -1e30 keeps this finite
        float mn1 = fmaxf(mrun1, mx1);
        float al0 = __expf(mrun0 - mn0);
        float al1 = __expf(mrun1 - mn1);
        mrun0 = mn0; mrun1 = mn1;

        float ls0 = 0.f, ls1 = 0.f;
        #pragma unroll
        for (int nf = 0; nf < 8; nf++){
            s[nf][0] = __expf(s[nf][0] - mn0); ls0 += s[nf][0];
            s[nf][1] = __expf(s[nf][1] - mn0); ls0 += s[nf][1];
            s[nf][2] = __expf(s[nf][2] - mn1); ls1 += s[nf][2];
            s[nf][3] = __expf(s[nf][3] - mn1); ls1 += s[nf][3];
            o[nf][0] *= al0; o[nf][1] *= al0; o[nf][2] *= al1; o[nf][3] *= al1;
        }
        ls0 += __shfl_xor_sync(0xffffffffu, ls0, 1);
        ls0 += __shfl_xor_sync(0xffffffffu, ls0, 2);
        ls1 += __shfl_xor_sync(0xffffffffu, ls1, 1);
        ls1 += __shfl_xor_sync(0xffffffffu, ls1, 2);
        l0 = l0*al0 + ls0;
        l1 = l1*al1 + ls1;

        // P -> warp-private smem (tf32), then O += P @ V
        #pragma unroll
        for (int nf = 0; nf < 8; nf++){
            int c  = nf*8 + 2*(lane&3);
            int rw = lane>>2;
            *(float2*)(&Pw[rw*68 + c])     = make_float2(to_tf32(s[nf][0]), to_tf32(s[nf][1]));
            *(float2*)(&Pw[(rw+8)*68 + c]) = make_float2(to_tf32(s[nf][2]), to_tf32(s[nf][3]));
        }
        __syncwarp();

        #pragma unroll
        for (int ks = 0; ks < 8; ks++){
            float pa[4];
            int c = ks*8 + (lane&3);
            pa[0] = Pw[(lane>>2)*68 + c];
            pa[1] = Pw[((lane>>2)+8)*68 + c];
            pa[2] = Pw[(lane>>2)*68 + c + 4];
            pa[3] = Pw[((lane>>2)+8)*68 + c + 4];
            #pragma unroll
            for (int nf = 0; nf < 8; nf++){
                int k = ks*8 + (lane&3);
                int d = nf*8 + (lane>>2);
                float b0 = Vs[k*68 + d];
                float b1 = Vs[(k+4)*68 + d];
                mma8(o[nf], pa, b0, b1);
            }
        }
        __syncwarp();
    }

    const float inv0 = 1.0f / l0;
    const float inv1 = 1.0f / l1;
    float* op0 = g_att + ((size_t)(b*N_ + r0))*C_ + h*64;
    float* op1 = op0 + (size_t)8*C_;
    #pragma unroll
    for (int nf = 0; nf < 8; nf++){
        int c = nf*8 + 2*(lane&3);
        *(float2*)(op0 + c) = make_float2(o[nf][0]*inv0, o[nf][1]*inv0);
        *(float2*)(op1 + c) = make_float2(o[nf][2]*inv1, o[nf][3]*inv1);
    }
}

// ---------------------------------------------------------------------------
extern "C" void kernel_launch(void* const* d_in, const int* in_sizes, int n_in,
                              void* d_out, int out_size)
{
    (void)in_sizes; (void)n_in; (void)out_size;
    const float* x      = (const float*)d_in[0];
    const int*   pmask  = (const int*)d_in[1];     // bool coerced to int32 by harness
    const float* alibi  = (const float*)d_in[2];
    const float* qkv_w  = (const float*)d_in[3];
    const float* qkv_b  = (const float*)d_in[4];
    const float* proj_w = (const float*)d_in[5];
    const float* proj_b = (const float*)d_in[6];
    float*       out    = (float*)d_out;

    const int ATTN_SMEM = (64*68 + 64*68 + 8*16*68) * 4;   // 69632 B
    cudaFuncSetAttribute(attn_kernel, cudaFuncAttributeMaxDynamicSharedMemorySize, ATTN_SMEM);

    float* att_ptr = nullptr;
    cudaGetSymbolAddress((void**)&att_ptr, g_att);

    dim3 blk(256);
    // 1) QKV projection + bias + transpose into g_q/g_k/g_v
    gemm_tf32_kernel<<<dim3(2304/128, 8192/128), blk>>>(x, qkv_w, qkv_b, nullptr,
                                                        8192, 768, 2304, 1);
    // 2) fused attention -> g_att [B,N,C]
    attn_kernel<<<dim3(N_/128, H_, B_), blk, ATTN_SMEM>>>(alibi, pmask);
    // 3) output projection + bias -> d_out
    gemm_tf32_kernel<<<dim3(768/128, 8192/128), blk>>>(att_ptr, proj_w, proj_b, out,
                                                       8192, 768, 768, 0);
}

// round 7
// speedup vs baseline: 1.1679x; 1.1679x over previous
#include <cuda_runtime.h>
#include <cstdint>

// Problem constants
#define B_  4
#define H_  12
#define N_  2048
#define D_  64
#define C_  768
#define BHND (B_*H_*N_*D_)

// Scratch (device globals — no allocation allowed)
__device__ float g_q[BHND];
__device__ float g_k[BHND];
__device__ float g_v[BHND];
__device__ float g_att[B_*N_*C_];

__device__ __forceinline__ float to_tf32(float x){
    uint32_t u = __float_as_uint(x);
    asm("cvt.rna.tf32.f32 %0, %0;" : "+r"(u));
    return __uint_as_float(u);
}

__device__ __forceinline__ void cp_async16(float* smem_dst, const float* gsrc){
    uint32_t s = (uint32_t)__cvta_generic_to_shared(smem_dst);
    asm volatile("cp.async.cg.shared.global [%0], [%1], 16;\n" :: "r"(s), "l"(gsrc));
}
__device__ __forceinline__ void cp_commit(){ asm volatile("cp.async.commit_group;\n"); }
template<int NN>
__device__ __forceinline__ void cp_wait(){ asm volatile("cp.async.wait_group %0;\n" :: "n"(NN)); }

// D = A(16x8, row) * B(8x8, col) + D ; tf32 inputs, fp32 accum
__device__ __forceinline__ void mma8(float d[4], const float a[4], float b0, float b1){
    asm volatile(
        "mma.sync.aligned.m16n8k8.row.col.f32.tf32.tf32.f32 "
        "{%0,%1,%2,%3},{%4,%5,%6,%7},{%8,%9},{%0,%1,%2,%3};\n"
        : "+f"(d[0]), "+f"(d[1]), "+f"(d[2]), "+f"(d[3])
        : "r"(__float_as_uint(a[0])), "r"(__float_as_uint(a[1])),
          "r"(__float_as_uint(a[2])), "r"(__float_as_uint(a[3])),
          "r"(__float_as_uint(b0)),   "r"(__float_as_uint(b1)));
}

// ---------------------------------------------------------------------------
// Generic TF32 GEMM:  out = A[M,K] @ W[K,NO] + bias
// 2-stage cp.async pipeline over K. tf32 cvt at fragment load.
// mode 0: row-major store; mode 1: QKV scatter into g_q/g_k/g_v [B,H,N,D]
// CTA tile 128x128, K-step 32, 8 warps (4x2), warp tile 32x64
// ---------------------------------------------------------------------------
#define SA_STRIDE 36
#define SB_STRIDE 132
#define SA_BUF (128*SA_STRIDE)   // 4608 floats
#define SB_BUF (32*SB_STRIDE)    // 4224 floats

__global__ __launch_bounds__(256) void gemm_tf32_kernel(
    const float* __restrict__ A, const float* __restrict__ W,
    const float* __restrict__ bias, float* __restrict__ out,
    int M, int K, int NO, int mode)
{
    extern __shared__ float smem[];
    float* sA = smem;                 // [2][128*36]
    float* sB = smem + 2*SA_BUF;      // [2][32*132]

    const int tid  = threadIdx.x;
    const int lane = tid & 31;
    const int warp = tid >> 5;
    const int wm   = warp & 3;
    const int wn   = warp >> 2;
    const int m0   = blockIdx.y * 128;
    const int n0   = blockIdx.x * 128;

    float acc[2][8][4];
    #pragma unroll
    for (int i = 0; i < 2; i++)
        #pragma unroll
        for (int j = 0; j < 8; j++)
            #pragma unroll
            for (int r = 0; r < 4; r++) acc[i][j][r] = 0.f;

    const int ra = tid >> 3;            // 0..31
    const int ca = (tid & 7) << 2;      // 0..28
    const int rb = tid >> 5;            // 0..7
    const int cb = (tid & 31) << 2;     // 0..124

    const int steps = K >> 5;           // 24

    // issue loads for a k-step into buffer `buf`
    auto load_step = [&](int k0, int buf){
        float* dA = sA + buf*SA_BUF;
        float* dB = sB + buf*SB_BUF;
        #pragma unroll
        for (int i = 0; i < 4; i++)
            cp_async16(&dA[(ra + i*32)*SA_STRIDE + ca],
                       A + (size_t)(m0 + ra + i*32)*K + k0 + ca);
        #pragma unroll
        for (int i = 0; i < 4; i++)
            cp_async16(&dB[(rb + i*8)*SB_STRIDE + cb],
                       W + (size_t)(k0 + rb + i*8)*NO + n0 + cb);
        cp_commit();
    };

    load_step(0, 0);
    load_step(32, 1);

    for (int it = 0; it < steps; it++){
        if (it + 1 < steps) cp_wait<1>(); else cp_wait<0>();
        __syncthreads();

        const float* cA = sA + (it & 1)*SA_BUF;
        const float* cB = sB + (it & 1)*SB_BUF;

        #pragma unroll
        for (int kk = 0; kk < 4; kk++){
            float af[2][4];
            #pragma unroll
            for (int mf = 0; mf < 2; mf++){
                int rbase = wm*32 + mf*16 + (lane>>2);
                int cbase = kk*8 + (lane&3);
                af[mf][0] = to_tf32(cA[rbase*SA_STRIDE + cbase]);
                af[mf][1] = to_tf32(cA[(rbase+8)*SA_STRIDE + cbase]);
                af[mf][2] = to_tf32(cA[rbase*SA_STRIDE + cbase + 4]);
                af[mf][3] = to_tf32(cA[(rbase+8)*SA_STRIDE + cbase + 4]);
            }
            #pragma unroll
            for (int nf = 0; nf < 8; nf++){
                int cc = wn*64 + nf*8 + (lane>>2);
                int rr = kk*8 + (lane&3);
                float b0 = to_tf32(cB[rr*SB_STRIDE + cc]);
                float b1 = to_tf32(cB[(rr+4)*SB_STRIDE + cc]);
                mma8(acc[0][nf], af[0], b0, b1);
                mma8(acc[1][nf], af[1], b0, b1);
            }
        }
        __syncthreads();
        if (it + 2 < steps) load_step((it+2) << 5, it & 1);
    }

    // epilogue
    #pragma unroll
    for (int mf = 0; mf < 2; mf++){
        #pragma unroll
        for (int nf = 0; nf < 8; nf++){
            #pragma unroll
            for (int rr = 0; rr < 2; rr++){
                int gm  = m0 + wm*32 + mf*16 + (lane>>2) + rr*8;
                int gn0 = n0 + wn*64 + nf*8 + 2*(lane&3);
                float v0 = acc[mf][nf][rr*2+0] + bias[gn0];
                float v1 = acc[mf][nf][rr*2+1] + bias[gn0+1];
                if (mode == 0){
                    *(float2*)(out + (size_t)gm*NO + gn0) = make_float2(v0, v1);
                } else {
                    int three = gn0 / 768;
                    int rem   = gn0 % 768;
                    int h     = rem / 64;
                    int d     = rem & 63;
                    int b     = gm >> 11;
                    int n     = gm & 2047;
                    float* base = (three == 0) ? g_q : (three == 1) ? g_k : g_v;
                    size_t idx = ((size_t)(b*H_ + h)*N_ + n)*D_ + d;
                    *(float2*)(base + idx) = make_float2(v0, v1);
                }
            }
        }
    }
}

// ---------------------------------------------------------------------------
// Fused attention: 128 q-rows/CTA, 8 warps x 16 rows. Key tile = 64.
// 2-stage cp.async pipeline on K/V tiles; tf32 conversion in-place in smem.
// alibi direct from gmem; mask via ballot; P relayout via warp-private smem.
// ---------------------------------------------------------------------------
#define KV_BUF (64*68)     // 4352 floats per buffer

__global__ __launch_bounds__(256) void attn_kernel(
    const float* __restrict__ alibi, const int* __restrict__ pmask)
{
    extern __shared__ float sm[];
    float* KsB = sm;                   // [2][64*68]
    float* VsB = sm + 2*KV_BUF;        // [2][64*68]
    float* Ps  = sm + 4*KV_BUF;        // 8 warps * 16*68

    const int tid  = threadIdx.x;
    const int lane = tid & 31;
    const int warp = tid >> 5;
    const int q0 = blockIdx.x * 128;
    const int h  = blockIdx.y;
    const int b  = blockIdx.z;
    const float scale = 0.125f;

    const int r0 = q0 + warp*16 + (lane>>2);
    const float* qp = g_q + (size_t)(b*H_ + h)*N_*D_;

    float qa[8][4];
    #pragma unroll
    for (int ks = 0; ks < 8; ks++){
        int c = ks*8 + (lane&3);
        qa[ks][0] = to_tf32(qp[(size_t)r0*64 + c]       * scale);
        qa[ks][1] = to_tf32(qp[(size_t)(r0+8)*64 + c]   * scale);
        qa[ks][2] = to_tf32(qp[(size_t)r0*64 + c+4]     * scale);
        qa[ks][3] = to_tf32(qp[(size_t)(r0+8)*64 + c+4] * scale);
    }

    float o[8][4];
    #pragma unroll
    for (int nf = 0; nf < 8; nf++){ o[nf][0]=o[nf][1]=o[nf][2]=o[nf][3]=0.f; }
    float mrun0 = -1e30f, mrun1 = -1e30f, l0 = 0.f, l1 = 0.f;

    const float* kbase = g_k + (size_t)(b*H_ + h)*N_*D_;
    const float* vbase = g_v + (size_t)(b*H_ + h)*N_*D_;
    const int* pm = pmask + b*N_;
    float* Pw = Ps + warp*(16*68);

    const int row_ld = tid >> 4;            // 0..15  (x4 iters -> 64 rows)
    const int c4_ld  = (tid & 15) << 2;     // 0..60

    auto load_tile = [&](int j0, int buf){
        float* dK = KsB + buf*KV_BUF;
        float* dV = VsB + buf*KV_BUF;
        #pragma unroll
        for (int i = 0; i < 4; i++){
            int row = row_ld + i*16;
            cp_async16(&dK[row*68 + c4_ld], kbase + (size_t)(j0+row)*64 + c4_ld);
            cp_async16(&dV[row*68 + c4_ld], vbase + (size_t)(j0+row)*64 + c4_ld);
        }
        cp_commit();
    };

    load_tile(0, 0);
    load_tile(64, 1);

    for (int it = 0; it < 32; it++){
        const int j0 = it << 6;
        if (it + 1 < 32) cp_wait<1>(); else cp_wait<0>();
        __syncthreads();

        float* Ks = KsB + (it & 1)*KV_BUF;
        float* Vs = VsB + (it & 1)*KV_BUF;

        // in-place tf32 conversion (each value reused by all 8 warps)
        #pragma unroll
        for (int i = 0; i < 4; i++){
            int row = row_ld + i*16;
            float4* pk = (float4*)&Ks[row*68 + c4_ld];
            float4 kv = *pk;
            kv.x=to_tf32(kv.x); kv.y=to_tf32(kv.y); kv.z=to_tf32(kv.z); kv.w=to_tf32(kv.w);
            *pk = kv;
            float4* pv = (float4*)&Vs[row*68 + c4_ld];
            float4 vv = *pv;
            vv.x=to_tf32(vv.x); vv.y=to_tf32(vv.y); vv.z=to_tf32(vv.z); vv.w=to_tf32(vv.w);
            *pv = vv;
        }
        __syncthreads();

        unsigned mlo = __ballot_sync(0xffffffffu, pm[j0 + lane]      != 0);
        unsigned mhi = __ballot_sync(0xffffffffu, pm[j0 + 32 + lane] != 0);

        // S = Q @ K^T
        float s[8][4];
        #pragma unroll
        for (int nf = 0; nf < 8; nf++){ s[nf][0]=s[nf][1]=s[nf][2]=s[nf][3]=0.f; }
        #pragma unroll
        for (int ks = 0; ks < 8; ks++){
            #pragma unroll
            for (int nf = 0; nf < 8; nf++){
                int n = nf*8 + (lane>>2);
                int c = ks*8 + (lane&3);
                float b0 = Ks[n*68 + c];
                float b1 = Ks[n*68 + c + 4];
                mma8(s[nf], qa[ks], b0, b1);
            }
        }

        // + alibi, mask
        const float* ab0 = alibi + ((size_t)((b*H_ + h)*N_ + r0))*N_ + j0;
        const float* ab1 = ab0 + (size_t)8*N_;
        #pragma unroll
        for (int nf = 0; nf < 8; nf++){
            int c = nf*8 + 2*(lane&3);
            unsigned bit0 = ((c   < 32) ? (mlo >> c)        : (mhi >> (c-32)))   & 1u;
            unsigned bit1 = ((c+1 < 32) ? (mlo >> (c+1))    : (mhi >> (c+1-32))) & 1u;
            float2 a0 = *(const float2*)(ab0 + c);
            float2 a1 = *(const float2*)(ab1 + c);
            s[nf][0] = bit0 ? -INFINITY : s[nf][0] + a0.x;
            s[nf][1] = bit1 ? -INFINITY : s[nf][1] + a0.y;
            s[nf][2] = bit0 ? -INFINITY : s[nf][2] + a1.x;
            s[nf][3] = bit1 ? -INFINITY : s[nf][3] + a1.y;
        }

        // online softmax (rows live in quads)
        float mx0 = -INFINITY, mx1 = -INFINITY;
        #pragma unroll
        for (int nf = 0; nf < 8; nf++){
            mx0 = fmaxf(mx0, fmaxf(s[nf][0], s[nf][1]));
            mx1 = fmaxf(mx1, fmaxf(s[nf][2], s[nf][3]));
        }
        mx0 = fmaxf(mx0, __shfl_xor_sync(0xffffffffu, mx0, 1));
        mx0 = fmaxf(mx0, __shfl_xor_sync(0xffffffffu, mx0, 2));
        mx1 = fmaxf(mx1, __shfl_xor_sync(0xffffffffu, mx1, 1));
        mx1 = fmaxf(mx1, __shfl_xor_sync(0xffffffffu, mx1, 2));
        float mn0 = fmaxf(mrun0, mx0);
        float mn1 = fmaxf(mrun1, mx1);
        float al0 = __expf(mrun0 - mn0);
        float al1 = __expf(mrun1 - mn1);
        mrun0 = mn0; mrun1 = mn1;

        float ls0 = 0.f, ls1 = 0.f;
        #pragma unroll
        for (int nf = 0; nf < 8; nf++){
            s[nf][0] = __expf(s[nf][0] - mn0); ls0 += s[nf][0];
            s[nf][1] = __expf(s[nf][1] - mn0); ls0 += s[nf][1];
            s[nf][2] = __expf(s[nf][2] - mn1); ls1 += s[nf][2];
            s[nf][3] = __expf(s[nf][3] - mn1); ls1 += s[nf][3];
            o[nf][0] *= al0; o[nf][1] *= al0; o[nf][2] *= al1; o[nf][3] *= al1;
        }
        ls0 += __shfl_xor_sync(0xffffffffu, ls0, 1);
        ls0 += __shfl_xor_sync(0xffffffffu, ls0, 2);
        ls1 += __shfl_xor_sync(0xffffffffu, ls1, 1);
        ls1 += __shfl_xor_sync(0xffffffffu, ls1, 2);
        l0 = l0*al0 + ls0;
        l1 = l1*al1 + ls1;

        // P -> warp-private smem (tf32), then O += P @ V
        #pragma unroll
        for (int nf = 0; nf < 8; nf++){
            int c  = nf*8 + 2*(lane&3);
            int rw = lane>>2;
            *(float2*)(&Pw[rw*68 + c])     = make_float2(to_tf32(s[nf][0]), to_tf32(s[nf][1]));
            *(float2*)(&Pw[(rw+8)*68 + c]) = make_float2(to_tf32(s[nf][2]), to_tf32(s[nf][3]));
        }
        __syncwarp();

        #pragma unroll
        for (int ks = 0; ks < 8; ks++){
            float pa[4];
            int c = ks*8 + (lane&3);
            pa[0] = Pw[(lane>>2)*68 + c];
            pa[1] = Pw[((lane>>2)+8)*68 + c];
            pa[2] = Pw[(lane>>2)*68 + c + 4];
            pa[3] = Pw[((lane>>2)+8)*68 + c + 4];
            #pragma unroll
            for (int nf = 0; nf < 8; nf++){
                int k = ks*8 + (lane&3);
                int d = nf*8 + (lane>>2);
                float b0 = Vs[k*68 + d];
                float b1 = Vs[(k+4)*68 + d];
                mma8(o[nf], pa, b0, b1);
            }
        }
        __syncthreads();
        if (it + 2 < 32) load_tile((it+2) << 6, it & 1);
    }

    const float inv0 = 1.0f / l0;
    const float inv1 = 1.0f / l1;
    float* op0 = g_att + ((size_t)(b*N_ + r0))*C_ + h*64;
    float* op1 = op0 + (size_t)8*C_;
    #pragma unroll
    for (int nf = 0; nf < 8; nf++){
        int c = nf*8 + 2*(lane&3);
        *(float2*)(op0 + c) = make_float2(o[nf][0]*inv0, o[nf][1]*inv0);
        *(float2*)(op1 + c) = make_float2(o[nf][2]*inv1, o[nf][3]*inv1);
    }
}

// ---------------------------------------------------------------------------
extern "C" void kernel_launch(void* const* d_in, const int* in_sizes, int n_in,
                              void* d_out, int out_size)
{
    (void)in_sizes; (void)n_in; (void)out_size;
    const float* x      = (const float*)d_in[0];
    const int*   pmask  = (const int*)d_in[1];     // bool coerced to int32
    const float* alibi  = (const float*)d_in[2];
    const float* qkv_w  = (const float*)d_in[3];
    const float* qkv_b  = (const float*)d_in[4];
    const float* proj_w = (const float*)d_in[5];
    const float* proj_b = (const float*)d_in[6];
    float*       out    = (float*)d_out;

    const int GEMM_SMEM = (2*SA_BUF + 2*SB_BUF) * 4;            // 70656 B
    const int ATTN_SMEM = (4*KV_BUF + 8*16*68) * 4;             // 104448 B
    cudaFuncSetAttribute(gemm_tf32_kernel, cudaFuncAttributeMaxDynamicSharedMemorySize, GEMM_SMEM);
    cudaFuncSetAttribute(attn_kernel, cudaFuncAttributeMaxDynamicSharedMemorySize, ATTN_SMEM);

    float* att_ptr = nullptr;
    cudaGetSymbolAddress((void**)&att_ptr, g_att);

    dim3 blk(256);
    // 1) QKV projection + bias + transpose into g_q/g_k/g_v
    gemm_tf32_kernel<<<dim3(2304/128, 8192/128), blk, GEMM_SMEM>>>(x, qkv_w, qkv_b, nullptr,
                                                                   8192, 768, 2304, 1);
    // 2) fused attention -> g_att [B,N,C]
    attn_kernel<<<dim3(N_/128, H_, B_), blk, ATTN_SMEM>>>(alibi, pmask);
    // 3) output projection + bias -> d_out
    gemm_tf32_kernel<<<dim3(768/128, 8192/128), blk, GEMM_SMEM>>>(att_ptr, proj_w, proj_b, out,
                                                                  8192, 768, 768, 0);
}

// round 8
// speedup vs baseline: 1.2649x; 1.0831x over previous
#include <cuda_runtime.h>
#include <cstdint>

// Problem constants
#define B_  4
#define H_  12
#define N_  2048
#define D_  64
#define C_  768
#define BHND (B_*H_*N_*D_)

// Scratch (device globals — no allocation allowed)
__device__ float g_q[BHND];
__device__ float g_k[BHND];
__device__ float g_v[BHND];
__device__ float g_att[B_*N_*C_];
__device__ float g_xc[B_*N_*C_];       // x, tf32, k-permuted
__device__ float g_wqkvT[3*C_*C_];     // qkv_w transposed [2304][768], tf32, k-permuted
__device__ float g_wprojT[C_*C_];      // proj_w transposed [768][768], tf32, k-permuted

__device__ __forceinline__ float to_tf32(float x){
    uint32_t u = __float_as_uint(x);
    asm("cvt.rna.tf32.f32 %0, %0;" : "+r"(u));
    return __uint_as_float(u);
}
__device__ __forceinline__ int perm8(int j){ return (j & ~7) + 2*(j&3) + ((j>>2)&1); }

__device__ __forceinline__ void cp_async16(float* smem_dst, const float* gsrc){
    uint32_t s = (uint32_t)__cvta_generic_to_shared(smem_dst);
    asm volatile("cp.async.cg.shared.global [%0], [%1], 16;\n" :: "r"(s), "l"(gsrc));
}
__device__ __forceinline__ void cp_commit(){ asm volatile("cp.async.commit_group;\n"); }
template<int NN>
__device__ __forceinline__ void cp_wait(){ asm volatile("cp.async.wait_group %0;\n" :: "n"(NN)); }

// D = A(16x8, row) * B(8x8, col) + D ; tf32 inputs, fp32 accum
__device__ __forceinline__ void mma8(float d[4], const float a[4], float b0, float b1){
    asm volatile(
        "mma.sync.aligned.m16n8k8.row.col.f32.tf32.tf32.f32 "
        "{%0,%1,%2,%3},{%4,%5,%6,%7},{%8,%9},{%0,%1,%2,%3};\n"
        : "+f"(d[0]), "+f"(d[1]), "+f"(d[2]), "+f"(d[3])
        : "r"(__float_as_uint(a[0])), "r"(__float_as_uint(a[1])),
          "r"(__float_as_uint(a[2])), "r"(__float_as_uint(a[3])),
          "r"(__float_as_uint(b0)),   "r"(__float_as_uint(b1)));
}

// ---------------------------------------------------------------------------
// Conversion kernels (one-time per launch)
// ---------------------------------------------------------------------------
// rows of length divisible by 8: tf32 + permute k within each 8-group
__global__ void cvt_perm_rows(const float* __restrict__ in, float* __restrict__ out, int n8){
    int g = blockIdx.x*blockDim.x + threadIdx.x;
    if (g >= n8) return;
    const float4* p = (const float4*)(in + (size_t)g*8);
    float4 u = p[0], v = p[1];
    float vals[8] = {u.x,u.y,u.z,u.w,v.x,v.y,v.z,v.w};
    float* o = out + (size_t)g*8;
    #pragma unroll
    for (int j = 0; j < 8; j++) o[2*(j&3)+((j>>2)&1)] = to_tf32(vals[j]);
}
// W[K][NO] -> Wt[NO][K] with k permuted within 8-groups, tf32
__global__ void cvt_perm_T(const float* __restrict__ w, float* __restrict__ wt, int K, int NO){
    int idx = blockIdx.x*blockDim.x + threadIdx.x;
    if (idx >= K*NO) return;
    int k = idx / NO, n = idx % NO;
    wt[(size_t)n*K + perm8(k)] = to_tf32(w[idx]);
}

// ---------------------------------------------------------------------------
// TF32 GEMM:  out = A[M,K] @ Wt[N,K]^T + bias   (A, Wt pre-tf32, k-permuted)
// mode 0: row-major fp32 store; mode 1: QKV scatter (q,k d-permuted tf32; v tf32)
// CTA tile 128x128, K-step 32, 2-stage cp.async, LDS.64 fragments, no cvt.
// ---------------------------------------------------------------------------
#define GSTR 36
#define GBUF (128*GSTR)   // 4608 floats per buffer (A and B same shape)

__global__ __launch_bounds__(256,2) void gemm_tf32_kernel(
    const float* __restrict__ A, const float* __restrict__ Wt,
    const float* __restrict__ bias, float* __restrict__ out,
    int M, int K, int NO, int mode)
{
    extern __shared__ float smem[];
    float* sA = smem;                 // [2][128*36]
    float* sB = smem + 2*GBUF;        // [2][128*36]

    const int tid  = threadIdx.x;
    const int lane = tid & 31;
    const int warp = tid >> 5;
    const int wm   = warp & 3;
    const int wn   = warp >> 2;
    const int m0   = blockIdx.y * 128;
    const int n0   = blockIdx.x * 128;
    const int R    = lane >> 2;
    const int t2   = (lane & 3) << 1;

    float acc[2][8][4];
    #pragma unroll
    for (int i = 0; i < 2; i++)
        #pragma unroll
        for (int j = 0; j < 8; j++)
            #pragma unroll
            for (int r = 0; r < 4; r++) acc[i][j][r] = 0.f;

    const int ra = tid >> 3;            // 0..31
    const int ca = (tid & 7) << 2;      // 0..28

    const int steps = K >> 5;

    auto load_step = [&](int k0, int buf){
        float* dA = sA + buf*GBUF;
        float* dB = sB + buf*GBUF;
        #pragma unroll
        for (int i = 0; i < 4; i++)
            cp_async16(&dA[(ra + i*32)*GSTR + ca],
                       A + (size_t)(m0 + ra + i*32)*K + k0 + ca);
        #pragma unroll
        for (int i = 0; i < 4; i++){
            int id = tid + i*256;
            int row = id >> 3;
            int c4  = (id & 7) << 2;
            cp_async16(&dB[row*GSTR + c4],
                       Wt + (size_t)(n0 + row)*K + k0 + c4);
        }
        cp_commit();
    };

    load_step(0, 0);
    load_step(32, 1);

    for (int it = 0; it < steps; it++){
        if (it + 1 < steps) cp_wait<1>(); else cp_wait<0>();
        __syncthreads();

        const float* cA = sA + (it & 1)*GBUF;
        const float* cB = sB + (it & 1)*GBUF;

        #pragma unroll
        for (int kk = 0; kk < 4; kk++){
            float af[2][4];
            #pragma unroll
            for (int mf = 0; mf < 2; mf++){
                int rbase = wm*32 + mf*16 + R;
                float2 p0 = *(const float2*)&cA[rbase*GSTR + kk*8 + t2];
                float2 p1 = *(const float2*)&cA[(rbase+8)*GSTR + kk*8 + t2];
                af[mf][0] = p0.x; af[mf][1] = p1.x; af[mf][2] = p0.y; af[mf][3] = p1.y;
            }
            #pragma unroll
            for (int nf = 0; nf < 8; nf++){
                int row = wn*64 + nf*8 + R;
                float2 bp = *(const float2*)&cB[row*GSTR + kk*8 + t2];
                mma8(acc[0][nf], af[0], bp.x, bp.y);
                mma8(acc[1][nf], af[1], bp.x, bp.y);
            }
        }
        __syncthreads();
        if (it + 2 < steps) load_step((it+2) << 5, it & 1);
    }

    // epilogue
    #pragma unroll
    for (int mf = 0; mf < 2; mf++){
        #pragma unroll
        for (int nf = 0; nf < 8; nf++){
            #pragma unroll
            for (int rr = 0; rr < 2; rr++){
                int gm  = m0 + wm*32 + mf*16 + R + rr*8;
                int gn0 = n0 + wn*64 + nf*8 + 2*(lane&3);
                float v0 = acc[mf][nf][rr*2+0] + bias[gn0];
                float v1 = acc[mf][nf][rr*2+1] + bias[gn0+1];
                if (mode == 0){
                    *(float2*)(out + (size_t)gm*NO + gn0) = make_float2(v0, v1);
                } else {
                    int three = gn0 / 768;
                    int rem   = gn0 % 768;
                    int h     = rem / 64;
                    int d     = rem & 63;
                    int b     = gm >> 11;
                    int n     = gm & 2047;
                    float* base = (three == 0) ? g_q : (three == 1) ? g_k : g_v;
                    size_t rowoff = ((size_t)(b*H_ + h)*N_ + n)*D_;
                    if (three < 2){   // q, k: d-permuted tf32
                        base[rowoff + perm8(d)]   = to_tf32(v0);
                        base[rowoff + perm8(d+1)] = to_tf32(v1);
                    } else {          // v: plain tf32
                        *(float2*)(base + rowoff + d) =
                            make_float2(to_tf32(v0), to_tf32(v1));
                    }
                }
            }
        }
    }
}

// ---------------------------------------------------------------------------
// Fused attention: 128 q-rows/CTA, 8 warps x 16 rows, key tile 64.
// cp.async pipelines for K/V (depth 2) and alibi (warp-private stage, depth 1).
// S initialized from alibi -> QK mma accumulates -> mask -> online softmax.
// PV A-fragments built via shuffles from S (no P smem).
// ---------------------------------------------------------------------------
#define KV_BUF (64*68)
#define NEG_INF __int_as_float(0xff800000)

__global__ __launch_bounds__(256,2) void attn_kernel(
    const float* __restrict__ alibi, const int* __restrict__ pmask)
{
    extern __shared__ float sm[];
    float* KsB = sm;                   // [2][64*68]
    float* VsB = sm + 2*KV_BUF;        // [2][64*68]
    float* ALs = sm + 4*KV_BUF;        // [128*68] alibi stage (warp-private rows)

    const int tid  = threadIdx.x;
    const int lane = tid & 31;
    const int warp = tid >> 5;
    const int q0 = blockIdx.x * 128;
    const int h  = blockIdx.y;
    const int b  = blockIdx.z;
    const float scale = 0.125f;
    const int R  = lane >> 2;
    const int t  = lane & 3;
    const int t2 = t << 1;

    const int r0 = q0 + warp*16 + R;
    const size_t bh = (size_t)(b*H_ + h);
    const float* qp = g_q + bh*N_*D_;

    // Q fragments (g_q is tf32 + d-permuted); *0.125 is exact in tf32
    float qa[8][4];
    #pragma unroll
    for (int ks = 0; ks < 8; ks++){
        float2 p0 = *(const float2*)&qp[(size_t)r0*64 + ks*8 + t2];
        float2 p1 = *(const float2*)&qp[(size_t)(r0+8)*64 + ks*8 + t2];
        qa[ks][0] = p0.x*scale; qa[ks][1] = p1.x*scale;
        qa[ks][2] = p0.y*scale; qa[ks][3] = p1.y*scale;
    }

    float o[8][4];
    #pragma unroll
    for (int nf = 0; nf < 8; nf++){ o[nf][0]=o[nf][1]=o[nf][2]=o[nf][3]=0.f; }
    float mrun0 = -1e30f, mrun1 = -1e30f, l0 = 0.f, l1 = 0.f;

    const float* kbase = g_k + bh*N_*D_;
    const float* vbase = g_v + bh*N_*D_;
    const float* abase = alibi + (bh*N_ + q0 + warp*16)*(size_t)N_;
    const int* pm = pmask + b*N_;

    const int row_ld = tid >> 4;
    const int c4_ld  = (tid & 15) << 2;

    auto load_kv = [&](int j0, int buf){
        float* dK = KsB + buf*KV_BUF;
        float* dV = VsB + buf*KV_BUF;
        #pragma unroll
        for (int i = 0; i < 4; i++){
            int row = row_ld + i*16;
            cp_async16(&dK[row*68 + c4_ld], kbase + (size_t)(j0+row)*64 + c4_ld);
            cp_async16(&dV[row*68 + c4_ld], vbase + (size_t)(j0+row)*64 + c4_ld);
        }
        cp_commit();
    };
    // warp-private alibi stage: warp w loads its own 16 rows
    auto load_al = [&](int j0){
        #pragma unroll
        for (int i = 0; i < 8; i++){
            int id = i*32 + lane;
            int rr = id >> 4;
            int cc = (id & 15) << 2;
            cp_async16(&ALs[(warp*16 + rr)*68 + cc],
                       abase + (size_t)rr*N_ + j0 + cc);
        }
        cp_commit();
    };

    load_kv(0, 0);     // G: KV0
    load_kv(64, 1);    // G: KV1
    load_al(0);        // G: AL0

    unsigned mlo = __ballot_sync(0xffffffffu, pm[lane]      != 0);
    unsigned mhi = __ballot_sync(0xffffffffu, pm[32 + lane] != 0);

    for (int it = 0; it < 32; it++){
        const int j0 = it << 6;
        if (it == 0 || it == 31) cp_wait<0>(); else cp_wait<1>();
        __syncthreads();

        const float* Ks = KsB + (it & 1)*KV_BUF;
        const float* Vs = VsB + (it & 1)*KV_BUF;

        // S init = alibi (from warp-private smem stage)
        float s[8][4];
        #pragma unroll
        for (int nf = 0; nf < 8; nf++){
            int c = nf*8 + t2;
            float2 a0 = *(const float2*)&ALs[(warp*16 + R)*68 + c];
            float2 a1 = *(const float2*)&ALs[(warp*16 + R + 8)*68 + c];
            s[nf][0] = a0.x; s[nf][1] = a0.y; s[nf][2] = a1.x; s[nf][3] = a1.y;
        }

        // S += Q @ K^T  (K tf32 + d-permuted -> single LDS.64 per B-frag)
        #pragma unroll
        for (int ks = 0; ks < 8; ks++){
            #pragma unroll
            for (int nf = 0; nf < 8; nf++){
                float2 bp = *(const float2*)&Ks[(nf*8 + R)*68 + ks*8 + t2];
                mma8(s[nf], qa[ks], bp.x, bp.y);
            }
        }

        // alibi stage consumed -> refill for next tile (warp-private)
        __syncwarp();
        if (it + 1 < 32) load_al(j0 + 64);

        // prefetch next tile's mask ballots
        unsigned nlo = 0, nhi = 0;
        if (it + 1 < 32){
            nlo = __ballot_sync(0xffffffffu, pm[j0 + 64 + lane] != 0);
            nhi = __ballot_sync(0xffffffffu, pm[j0 + 96 + lane] != 0);
        }

        // apply padding mask
        #pragma unroll
        for (int nf = 0; nf < 8; nf++){
            int c = nf*8 + t2;
            unsigned bit0 = ((c   < 32) ? (mlo >> c)      : (mhi >> (c-32)))   & 1u;
            unsigned bit1 = ((c+1 < 32) ? (mlo >> (c+1))  : (mhi >> (c+1-32))) & 1u;
            if (bit0){ s[nf][0] = NEG_INF; s[nf][2] = NEG_INF; }
            if (bit1){ s[nf][1] = NEG_INF; s[nf][3] = NEG_INF; }
        }

        // online softmax (rows live in quads)
        float mx0 = -INFINITY, mx1 = -INFINITY;
        #pragma unroll
        for (int nf = 0; nf < 8; nf++){
            mx0 = fmaxf(mx0, fmaxf(s[nf][0], s[nf][1]));
            mx1 = fmaxf(mx1, fmaxf(s[nf][2], s[nf][3]));
        }
        mx0 = fmaxf(mx0, __shfl_xor_sync(0xffffffffu, mx0, 1));
        mx0 = fmaxf(mx0, __shfl_xor_sync(0xffffffffu, mx0, 2));
        mx1 = fmaxf(mx1, __shfl_xor_sync(0xffffffffu, mx1, 1));
        mx1 = fmaxf(mx1, __shfl_xor_sync(0xffffffffu, mx1, 2));
        float mn0 = fmaxf(mrun0, mx0);
        float mn1 = fmaxf(mrun1, mx1);
        float al0 = __expf(mrun0 - mn0);
        float al1 = __expf(mrun1 - mn1);
        mrun0 = mn0; mrun1 = mn1;

        float ls0 = 0.f, ls1 = 0.f;
        #pragma unroll
        for (int nf = 0; nf < 8; nf++){
            s[nf][0] = __expf(s[nf][0] - mn0); ls0 += s[nf][0];
            s[nf][1] = __expf(s[nf][1] - mn0); ls0 += s[nf][1];
            s[nf][2] = __expf(s[nf][2] - mn1); ls1 += s[nf][2];
            s[nf][3] = __expf(s[nf][3] - mn1); ls1 += s[nf][3];
            o[nf][0] *= al0; o[nf][1] *= al0; o[nf][2] *= al1; o[nf][3] *= al1;
        }
        ls0 += __shfl_xor_sync(0xffffffffu, ls0, 1);
        ls0 += __shfl_xor_sync(0xffffffffu, ls0, 2);
        ls1 += __shfl_xor_sync(0xffffffffu, ls1, 1);
        ls1 += __shfl_xor_sync(0xffffffffu, ls1, 2);
        l0 = l0*al0 + ls0;
        l1 = l1*al1 + ls1;

        // O += P @ V : build A-fragments from S via shuffles (no smem)
        const int Lb  = R*4 + (t >> 1);
        const int Lb2 = Lb + 2;
        const bool hi = t & 1;
        #pragma unroll
        for (int ks = 0; ks < 8; ks++){
            float v00 = __shfl_sync(0xffffffffu, s[ks][0], Lb);
            float v01 = __shfl_sync(0xffffffffu, s[ks][1], Lb);
            float v20 = __shfl_sync(0xffffffffu, s[ks][2], Lb);
            float v21 = __shfl_sync(0xffffffffu, s[ks][3], Lb);
            float w00 = __shfl_sync(0xffffffffu, s[ks][0], Lb2);
            float w01 = __shfl_sync(0xffffffffu, s[ks][1], Lb2);
            float w20 = __shfl_sync(0xffffffffu, s[ks][2], Lb2);
            float w21 = __shfl_sync(0xffffffffu, s[ks][3], Lb2);
            float pa[4];
            pa[0] = to_tf32(hi ? v01 : v00);
            pa[1] = to_tf32(hi ? v21 : v20);
            pa[2] = to_tf32(hi ? w01 : w00);
            pa[3] = to_tf32(hi ? w21 : w20);
            #pragma unroll
            for (int nf = 0; nf < 8; nf++){
                int k = ks*8 + t;
                int d = nf*8 + R;
                float b0 = Vs[k*68 + d];
                float b1 = Vs[(k+4)*68 + d];
                mma8(o[nf], pa, b0, b1);
            }
        }
        __syncthreads();
        if (it + 2 < 32) load_kv((it+2) << 6, it & 1);
        mlo = nlo; mhi = nhi;
    }

    // epilogue: normalized O -> g_att as tf32, column-permuted within 8-groups
    const float inv0 = 1.0f / l0;
    const float inv1 = 1.0f / l1;
    float* orow0 = g_att + ((size_t)(b*N_ + r0))*C_;
    float* orow1 = orow0 + (size_t)8*C_;
    #pragma unroll
    for (int nf = 0; nf < 8; nf++){
        int c = h*64 + nf*8 + t2;
        orow0[perm8(c)]   = to_tf32(o[nf][0]*inv0);
        orow0[perm8(c+1)] = to_tf32(o[nf][1]*inv0);
        orow1[perm8(c)]   = to_tf32(o[nf][2]*inv1);
        orow1[perm8(c+1)] = to_tf32(o[nf][3]*inv1);
    }
}

// ---------------------------------------------------------------------------
extern "C" void kernel_launch(void* const* d_in, const int* in_sizes, int n_in,
                              void* d_out, int out_size)
{
    (void)in_sizes; (void)n_in; (void)out_size;
    const float* x      = (const float*)d_in[0];
    const int*   pmask  = (const int*)d_in[1];     // bool coerced to int32
    const float* alibi  = (const float*)d_in[2];
    const float* qkv_w  = (const float*)d_in[3];
    const float* qkv_b  = (const float*)d_in[4];
    const float* proj_w = (const float*)d_in[5];
    const float* proj_b = (const float*)d_in[6];
    float*       out    = (float*)d_out;

    const int GEMM_SMEM = (4*GBUF) * 4;                       // 73728 B
    const int ATTN_SMEM = (4*KV_BUF + 128*68) * 4;            // 104448 B
    cudaFuncSetAttribute(gemm_tf32_kernel, cudaFuncAttributeMaxDynamicSharedMemorySize, GEMM_SMEM);
    cudaFuncSetAttribute(attn_kernel, cudaFuncAttributeMaxDynamicSharedMemorySize, ATTN_SMEM);

    float *att_ptr = nullptr, *xc_ptr = nullptr, *wqkvT_ptr = nullptr, *wprojT_ptr = nullptr;
    cudaGetSymbolAddress((void**)&att_ptr,    g_att);
    cudaGetSymbolAddress((void**)&xc_ptr,     g_xc);
    cudaGetSymbolAddress((void**)&wqkvT_ptr,  g_wqkvT);
    cudaGetSymbolAddress((void**)&wprojT_ptr, g_wprojT);

    dim3 blk(256);
    // 0) one-time conversions: tf32 + contraction-dim permutation
    {
        int n8 = (B_*N_*C_) / 8;                               // 786432
        cvt_perm_rows<<<(n8 + 255)/256, blk>>>(x, xc_ptr, n8);
        int nq = C_ * 3*C_;                                    // 1769472
        cvt_perm_T<<<(nq + 255)/256, blk>>>(qkv_w, wqkvT_ptr, C_, 3*C_);
        int np = C_ * C_;                                      // 589824
        cvt_perm_T<<<(np + 255)/256, blk>>>(proj_w, wprojT_ptr, C_, C_);
    }
    // 1) QKV projection + bias + scatter (q,k d-permuted tf32; v tf32)
    gemm_tf32_kernel<<<dim3(2304/128, 8192/128), blk, GEMM_SMEM>>>(
        xc_ptr, wqkvT_ptr, qkv_b, nullptr, 8192, 768, 2304, 1);
    // 2) fused attention -> g_att (tf32, k-permuted)
    attn_kernel<<<dim3(N_/128, H_, B_), blk, ATTN_SMEM>>>(alibi, pmask);
    // 3) output projection + bias -> d_out (fp32)
    gemm_tf32_kernel<<<dim3(768/128, 8192/128), blk, GEMM_SMEM>>>(
        att_ptr, wprojT_ptr, proj_b, out, 8192, 768, 768, 0);
}

// round 9
// speedup vs baseline: 1.6848x; 1.3319x over previous
#include <cuda_runtime.h>
#include <cstdint>

// Problem constants
#define B_  4
#define H_  12
#define N_  2048
#define D_  64
#define C_  768
#define BHND (B_*H_*N_*D_)

// Scratch (device globals — no allocation allowed)
__device__ float g_q[BHND];            // [b,h][n][d]  tf32, d-permuted
__device__ float g_k[BHND];            // [b,h][n][d]  tf32, d-permuted
__device__ float g_v[BHND];            // [b,h][d][n]  tf32, key(n)-permuted (TRANSPOSED)
__device__ float g_att[B_*N_*C_];      // [b,n][c]     tf32, c-permuted
__device__ float g_xc[B_*N_*C_];       // x, tf32, k-permuted
__device__ float g_wqkvT[3*C_*C_];     // qkv_w transposed [2304][768], tf32, k-permuted
__device__ float g_wprojT[C_*C_];      // proj_w transposed [768][768], tf32, k-permuted

#define LOG2E 1.4426950408889634f

__device__ __forceinline__ float to_tf32(float x){
    uint32_t u = __float_as_uint(x);
    asm("cvt.rna.tf32.f32 %0, %0;" : "+r"(u));
    return __uint_as_float(u);
}
__device__ __forceinline__ float ex2(float x){
    float r;
    asm("ex2.approx.ftz.f32 %0, %1;" : "=f"(r) : "f"(x));
    return r;
}
__device__ __forceinline__ int perm8(int j){ return (j & ~7) + 2*(j&3) + ((j>>2)&1); }

__device__ __forceinline__ void cp_async16(float* smem_dst, const float* gsrc){
    uint32_t s = (uint32_t)__cvta_generic_to_shared(smem_dst);
    asm volatile("cp.async.cg.shared.global [%0], [%1], 16;\n" :: "r"(s), "l"(gsrc));
}
__device__ __forceinline__ void cp_commit(){ asm volatile("cp.async.commit_group;\n"); }
template<int NN>
__device__ __forceinline__ void cp_wait(){ asm volatile("cp.async.wait_group %0;\n" :: "n"(NN)); }

// D = A(16x8, row) * B(8x8, col) + D ; tf32 inputs, fp32 accum
__device__ __forceinline__ void mma8(float d[4], const float a[4], float b0, float b1){
    asm volatile(
        "mma.sync.aligned.m16n8k8.row.col.f32.tf32.tf32.f32 "
        "{%0,%1,%2,%3},{%4,%5,%6,%7},{%8,%9},{%0,%1,%2,%3};\n"
        : "+f"(d[0]), "+f"(d[1]), "+f"(d[2]), "+f"(d[3])
        : "r"(__float_as_uint(a[0])), "r"(__float_as_uint(a[1])),
          "r"(__float_as_uint(a[2])), "r"(__float_as_uint(a[3])),
          "r"(__float_as_uint(b0)),   "r"(__float_as_uint(b1)));
}

// ---------------------------------------------------------------------------
// Conversion kernels (one-time per launch)
// ---------------------------------------------------------------------------
__global__ void cvt_perm_rows(const float* __restrict__ in, float* __restrict__ out, int n8){
    int g = blockIdx.x*blockDim.x + threadIdx.x;
    if (g >= n8) return;
    const float4* p = (const float4*)(in + (size_t)g*8);
    float4 u = p[0], v = p[1];
    float vals[8] = {u.x,u.y,u.z,u.w,v.x,v.y,v.z,v.w};
    float* o = out + (size_t)g*8;
    #pragma unroll
    for (int j = 0; j < 8; j++) o[2*(j&3)+((j>>2)&1)] = to_tf32(vals[j]);
}
__global__ void cvt_perm_T(const float* __restrict__ w, float* __restrict__ wt, int K, int NO){
    int idx = blockIdx.x*blockDim.x + threadIdx.x;
    if (idx >= K*NO) return;
    int k = idx / NO, n = idx % NO;
    wt[(size_t)n*K + perm8(k)] = to_tf32(w[idx]);
}

// ---------------------------------------------------------------------------
// TF32 GEMM:  out = A[M,K] @ Wt[N,K]^T + bias   (A, Wt pre-tf32, k-permuted)
// 128 threads, 4 warps (2x2), warp tile 64x64 -> 128B smem per mma.
// mode 0: row-major fp32 store; mode 1: QKV scatter (q,k d-perm; v transposed)
// ---------------------------------------------------------------------------
#define GSTR 40
#define GBUF (128*GSTR)   // 5120 floats per buffer

__global__ __launch_bounds__(128,2) void gemm_tf32_kernel(
    const float* __restrict__ A, const float* __restrict__ Wt,
    const float* __restrict__ bias, float* __restrict__ out,
    int M, int K, int NO, int mode)
{
    extern __shared__ float smem[];
    float* sA = smem;                 // [2][128*40]
    float* sB = smem + 2*GBUF;        // [2][128*40]

    const int tid  = threadIdx.x;
    const int lane = tid & 31;
    const int warp = tid >> 5;        // 0..3
    const int wm   = warp & 1;        // m offset wm*64
    const int wn   = warp >> 1;       // n offset wn*64
    const int m0   = blockIdx.y * 128;
    const int n0   = blockIdx.x * 128;
    const int R    = lane >> 2;
    const int t2   = (lane & 3) << 1;

    float acc[4][8][4];
    #pragma unroll
    for (int i = 0; i < 4; i++)
        #pragma unroll
        for (int j = 0; j < 8; j++)
            #pragma unroll
            for (int r = 0; r < 4; r++) acc[i][j][r] = 0.f;

    const int steps = K >> 5;

    auto load_step = [&](int k0, int buf){
        float* dA = sA + buf*GBUF;
        float* dB = sB + buf*GBUF;
        #pragma unroll
        for (int i = 0; i < 8; i++){
            int id  = tid + i*128;
            int row = id >> 3;            // 0..127
            int c4  = (id & 7) << 2;      // 0..28
            cp_async16(&dA[row*GSTR + c4], A  + (size_t)(m0 + row)*K + k0 + c4);
        }
        #pragma unroll
        for (int i = 0; i < 8; i++){
            int id  = tid + i*128;
            int row = id >> 3;
            int c4  = (id & 7) << 2;
            cp_async16(&dB[row*GSTR + c4], Wt + (size_t)(n0 + row)*K + k0 + c4);
        }
        cp_commit();
    };

    load_step(0, 0);
    load_step(32, 1);

    for (int it = 0; it < steps; it++){
        if (it + 1 < steps) cp_wait<1>(); else cp_wait<0>();
        __syncthreads();

        const float* cA = sA + (it & 1)*GBUF;
        const float* cB = sB + (it & 1)*GBUF;

        #pragma unroll
        for (int kk = 0; kk < 4; kk++){
            float af[4][4];
            #pragma unroll
            for (int mf = 0; mf < 4; mf++){
                int rbase = wm*64 + mf*16 + R;
                float2 p0 = *(const float2*)&cA[rbase*GSTR + kk*8 + t2];
                float2 p1 = *(const float2*)&cA[(rbase+8)*GSTR + kk*8 + t2];
                af[mf][0] = p0.x; af[mf][1] = p1.x; af[mf][2] = p0.y; af[mf][3] = p1.y;
            }
            #pragma unroll
            for (int nf = 0; nf < 8; nf++){
                int row = wn*64 + nf*8 + R;
                float2 bp = *(const float2*)&cB[row*GSTR + kk*8 + t2];
                #pragma unroll
                for (int mf = 0; mf < 4; mf++)
                    mma8(acc[mf][nf], af[mf], bp.x, bp.y);
            }
        }
        __syncthreads();
        if (it + 2 < steps) load_step((it+2) << 5, it & 1);
    }

    // epilogue
    #pragma unroll
    for (int mf = 0; mf < 4; mf++){
        #pragma unroll
        for (int nf = 0; nf < 8; nf++){
            #pragma unroll
            for (int rr = 0; rr < 2; rr++){
                int gm  = m0 + wm*64 + mf*16 + R + rr*8;
                int gn0 = n0 + wn*64 + nf*8 + t2;
                float v0 = acc[mf][nf][rr*2+0] + bias[gn0];
                float v1 = acc[mf][nf][rr*2+1] + bias[gn0+1];
                if (mode == 0){
                    *(float2*)(out + (size_t)gm*NO + gn0) = make_float2(v0, v1);
                } else {
                    int three = gn0 / 768;
                    int rem   = gn0 % 768;
                    int h     = rem / 64;
                    int d     = rem & 63;
                    int b     = gm >> 11;
                    int n     = gm & 2047;
                    size_t bh = (size_t)(b*H_ + h);
                    if (three == 0){
                        size_t ro = (bh*N_ + n)*D_;
                        g_q[ro + perm8(d)]   = to_tf32(v0);
                        g_q[ro + perm8(d+1)] = to_tf32(v1);
                    } else if (three == 1){
                        size_t ro = (bh*N_ + n)*D_;
                        g_k[ro + perm8(d)]   = to_tf32(v0);
                        g_k[ro + perm8(d+1)] = to_tf32(v1);
                    } else {  // v: transposed [d][n], key-permuted columns
                        size_t vo = (bh*D_ + d)*N_ + perm8(n);
                        g_v[vo]      = to_tf32(v0);
                        g_v[vo + N_] = to_tf32(v1);
                    }
                }
            }
        }
    }
}

// ---------------------------------------------------------------------------
// Fused attention: 128 q-rows/CTA, 8 warps x 16 rows, key tile 64.
// K smem [key][d] stride 72 (conflict-free LDS.64); V smem [d][key] stride 72.
// exp2 domain: Q pre-scaled by 0.125*log2e, alibi scaled by log2e at S-init.
// ---------------------------------------------------------------------------
#define KSTR 72
#define KV_BUF (64*KSTR)     // 4608 floats
#define ASTR 72
#define NEG_INF __int_as_float(0xff800000)

__global__ __launch_bounds__(256,2) void attn_kernel(
    const float* __restrict__ alibi, const int* __restrict__ pmask)
{
    extern __shared__ float sm[];
    float* KsB = sm;                   // [2][64*72]
    float* VsB = sm + 2*KV_BUF;        // [2][64*72]
    float* ALs = sm + 4*KV_BUF;        // [128*72] alibi stage (warp-private rows)

    const int tid  = threadIdx.x;
    const int lane = tid & 31;
    const int warp = tid >> 5;
    const int q0 = blockIdx.x * 128;
    const int h  = blockIdx.y;
    const int b  = blockIdx.z;
    const int R  = lane >> 2;
    const int t  = lane & 3;
    const int t2 = t << 1;

    const int r0 = q0 + warp*16 + R;
    const size_t bh = (size_t)(b*H_ + h);
    const float* qp = g_q + bh*N_*D_;

    // Q fragments: tf32(q * 0.125 * log2e)
    const float qscale = 0.125f * LOG2E;
    float qa[8][4];
    #pragma unroll
    for (int ks = 0; ks < 8; ks++){
        float2 p0 = *(const float2*)&qp[(size_t)r0*64 + ks*8 + t2];
        float2 p1 = *(const float2*)&qp[(size_t)(r0+8)*64 + ks*8 + t2];
        qa[ks][0] = to_tf32(p0.x*qscale); qa[ks][1] = to_tf32(p1.x*qscale);
        qa[ks][2] = to_tf32(p0.y*qscale); qa[ks][3] = to_tf32(p1.y*qscale);
    }

    float o[8][4];
    #pragma unroll
    for (int nf = 0; nf < 8; nf++){ o[nf][0]=o[nf][1]=o[nf][2]=o[nf][3]=0.f; }
    float mrun0 = -1e30f, mrun1 = -1e30f, l0 = 0.f, l1 = 0.f;

    const float* kbase = g_k + bh*N_*D_;            // [key][d]
    const float* vbase = g_v + bh*(size_t)D_*N_;    // [d][key]
    const float* abase = alibi + (bh*N_ + q0 + warp*16)*(size_t)N_;
    const int* pm = pmask + b*N_;

    auto load_kv = [&](int j0, int buf){
        float* dK = KsB + buf*KV_BUF;
        float* dV = VsB + buf*KV_BUF;
        #pragma unroll
        for (int i = 0; i < 4; i++){
            int id  = tid + i*256;
            int row = id >> 4;            // 0..63
            int c4  = (id & 15) << 2;     // 0..60
            cp_async16(&dK[row*KSTR + c4], kbase + (size_t)(j0+row)*64 + c4);
            cp_async16(&dV[row*KSTR + c4], vbase + (size_t)row*N_ + j0 + c4);
        }
        cp_commit();
    };
    auto load_al = [&](int j0){
        #pragma unroll
        for (int i = 0; i < 8; i++){
            int id = i*32 + lane;
            int rr = id >> 4;
            int cc = (id & 15) << 2;
            cp_async16(&ALs[(warp*16 + rr)*ASTR + cc],
                       abase + (size_t)rr*N_ + j0 + cc);
        }
        cp_commit();
    };

    load_kv(0, 0);
    load_kv(64, 1);
    load_al(0);

    unsigned mlo = __ballot_sync(0xffffffffu, pm[lane]      != 0);
    unsigned mhi = __ballot_sync(0xffffffffu, pm[32 + lane] != 0);

    for (int it = 0; it < 32; it++){
        const int j0 = it << 6;
        if (it == 0 || it == 31) cp_wait<0>(); else cp_wait<1>();
        __syncthreads();

        const float* Ks = KsB + (it & 1)*KV_BUF;
        const float* Vs = VsB + (it & 1)*KV_BUF;

        // S init = alibi * log2e
        float s[8][4];
        #pragma unroll
        for (int nf = 0; nf < 8; nf++){
            int c = nf*8 + t2;
            float2 a0 = *(const float2*)&ALs[(warp*16 + R)*ASTR + c];
            float2 a1 = *(const float2*)&ALs[(warp*16 + R + 8)*ASTR + c];
            s[nf][0] = a0.x*LOG2E; s[nf][1] = a0.y*LOG2E;
            s[nf][2] = a1.x*LOG2E; s[nf][3] = a1.y*LOG2E;
        }

        // S += Q' @ K^T
        #pragma unroll
        for (int ks = 0; ks < 8; ks++){
            #pragma unroll
            for (int nf = 0; nf < 8; nf++){
                float2 bp = *(const float2*)&Ks[(nf*8 + R)*KSTR + ks*8 + t2];
                mma8(s[nf], qa[ks], bp.x, bp.y);
            }
        }

        __syncwarp();
        if (it + 1 < 32) load_al(j0 + 64);

        unsigned nlo = 0, nhi = 0;
        if (it + 1 < 32){
            nlo = __ballot_sync(0xffffffffu, pm[j0 + 64 + lane] != 0);
            nhi = __ballot_sync(0xffffffffu, pm[j0 + 96 + lane] != 0);
        }

        // padding mask
        #pragma unroll
        for (int nf = 0; nf < 8; nf++){
            int c = nf*8 + t2;
            unsigned bit0 = ((c   < 32) ? (mlo >> c)      : (mhi >> (c-32)))   & 1u;
            unsigned bit1 = ((c+1 < 32) ? (mlo >> (c+1))  : (mhi >> (c+1-32))) & 1u;
            if (bit0){ s[nf][0] = NEG_INF; s[nf][2] = NEG_INF; }
            if (bit1){ s[nf][1] = NEG_INF; s[nf][3] = NEG_INF; }
        }

        // online softmax in log2 domain
        float mx0 = -INFINITY, mx1 = -INFINITY;
        #pragma unroll
        for (int nf = 0; nf < 8; nf++){
            mx0 = fmaxf(mx0, fmaxf(s[nf][0], s[nf][1]));
            mx1 = fmaxf(mx1, fmaxf(s[nf][2], s[nf][3]));
        }
        mx0 = fmaxf(mx0, __shfl_xor_sync(0xffffffffu, mx0, 1));
        mx0 = fmaxf(mx0, __shfl_xor_sync(0xffffffffu, mx0, 2));
        mx1 = fmaxf(mx1, __shfl_xor_sync(0xffffffffu, mx1, 1));
        mx1 = fmaxf(mx1, __shfl_xor_sync(0xffffffffu, mx1, 2));
        float mn0 = fmaxf(mrun0, mx0);
        float mn1 = fmaxf(mrun1, mx1);
        float al0 = ex2(mrun0 - mn0);
        float al1 = ex2(mrun1 - mn1);
        mrun0 = mn0; mrun1 = mn1;

        float ls0 = 0.f, ls1 = 0.f;
        #pragma unroll
        for (int nf = 0; nf < 8; nf++){
            s[nf][0] = ex2(s[nf][0] - mn0); ls0 += s[nf][0];
            s[nf][1] = ex2(s[nf][1] - mn0); ls0 += s[nf][1];
            s[nf][2] = ex2(s[nf][2] - mn1); ls1 += s[nf][2];
            s[nf][3] = ex2(s[nf][3] - mn1); ls1 += s[nf][3];
            o[nf][0] *= al0; o[nf][1] *= al0; o[nf][2] *= al1; o[nf][3] *= al1;
        }
        ls0 += __shfl_xor_sync(0xffffffffu, ls0, 1);
        ls0 += __shfl_xor_sync(0xffffffffu, ls0, 2);
        ls1 += __shfl_xor_sync(0xffffffffu, ls1, 1);
        ls1 += __shfl_xor_sync(0xffffffffu, ls1, 2);
        l0 = l0*al0 + ls0;
        l1 = l1*al1 + ls1;

        // O += P @ V : A-frags via shuffles; B-frags single LDS.64 from V^T
        const int Lb  = R*4 + (t >> 1);
        const int Lb2 = Lb + 2;
        const bool hi = t & 1;
        #pragma unroll
        for (int ks = 0; ks < 8; ks++){
            float v00 = __shfl_sync(0xffffffffu, s[ks][0], Lb);
            float v01 = __shfl_sync(0xffffffffu, s[ks][1], Lb);
            float v20 = __shfl_sync(0xffffffffu, s[ks][2], Lb);
            float v21 = __shfl_sync(0xffffffffu, s[ks][3], Lb);
            float w00 = __shfl_sync(0xffffffffu, s[ks][0], Lb2);
            float w01 = __shfl_sync(0xffffffffu, s[ks][1], Lb2);
            float w20 = __shfl_sync(0xffffffffu, s[ks][2], Lb2);
            float w21 = __shfl_sync(0xffffffffu, s[ks][3], Lb2);
            float pa[4];
            pa[0] = to_tf32(hi ? v01 : v00);
            pa[1] = to_tf32(hi ? v21 : v20);
            pa[2] = to_tf32(hi ? w01 : w00);
            pa[3] = to_tf32(hi ? w21 : w20);
            #pragma unroll
            for (int nf = 0; nf < 8; nf++){
                // V^T smem: row = d (nf*8+R), cols = keys (permuted: k, k+4 adjacent)
                float2 bp = *(const float2*)&Vs[(nf*8 + R)*KSTR + ks*8 + t2];
                mma8(o[nf], pa, bp.x, bp.y);
            }
        }
        __syncthreads();
        if (it + 2 < 32) load_kv((it+2) << 6, it & 1);
        mlo = nlo; mhi = nhi;
    }

    // epilogue: normalized O -> g_att as tf32, column-permuted
    const float inv0 = 1.0f / l0;
    const float inv1 = 1.0f / l1;
    float* orow0 = g_att + ((size_t)(b*N_ + r0))*C_;
    float* orow1 = orow0 + (size_t)8*C_;
    #pragma unroll
    for (int nf = 0; nf < 8; nf++){
        int c = h*64 + nf*8 + t2;
        orow0[perm8(c)]   = to_tf32(o[nf][0]*inv0);
        orow0[perm8(c+1)] = to_tf32(o[nf][1]*inv0);
        orow1[perm8(c)]   = to_tf32(o[nf][2]*inv1);
        orow1[perm8(c+1)] = to_tf32(o[nf][3]*inv1);
    }
}

// ---------------------------------------------------------------------------
extern "C" void kernel_launch(void* const* d_in, const int* in_sizes, int n_in,
                              void* d_out, int out_size)
{
    (void)in_sizes; (void)n_in; (void)out_size;
    const float* x      = (const float*)d_in[0];
    const int*   pmask  = (const int*)d_in[1];
    const float* alibi  = (const float*)d_in[2];
    const float* qkv_w  = (const float*)d_in[3];
    const float* qkv_b  = (const float*)d_in[4];
    const float* proj_w = (const float*)d_in[5];
    const float* proj_b = (const float*)d_in[6];
    float*       out    = (float*)d_out;

    const int GEMM_SMEM = (4*GBUF) * 4;                       // 81920 B
    const int ATTN_SMEM = (4*KV_BUF + 128*ASTR) * 4;          // 110592 B
    cudaFuncSetAttribute(gemm_tf32_kernel, cudaFuncAttributeMaxDynamicSharedMemorySize, GEMM_SMEM);
    cudaFuncSetAttribute(attn_kernel, cudaFuncAttributeMaxDynamicSharedMemorySize, ATTN_SMEM);

    float *att_ptr = nullptr, *xc_ptr = nullptr, *wqkvT_ptr = nullptr, *wprojT_ptr = nullptr;
    cudaGetSymbolAddress((void**)&att_ptr,    g_att);
    cudaGetSymbolAddress((void**)&xc_ptr,     g_xc);
    cudaGetSymbolAddress((void**)&wqkvT_ptr,  g_wqkvT);
    cudaGetSymbolAddress((void**)&wprojT_ptr, g_wprojT);

    // 0) one-time conversions: tf32 + contraction-dim permutation
    {
        int n8 = (B_*N_*C_) / 8;
        cvt_perm_rows<<<(n8 + 255)/256, 256>>>(x, xc_ptr, n8);
        int nq = C_ * 3*C_;
        cvt_perm_T<<<(nq + 255)/256, 256>>>(qkv_w, wqkvT_ptr, C_, 3*C_);
        int np = C_ * C_;
        cvt_perm_T<<<(np + 255)/256, 256>>>(proj_w, wprojT_ptr, C_, C_);
    }
    // 1) QKV projection + bias + scatter (q,k d-perm; v transposed key-perm)
    gemm_tf32_kernel<<<dim3(2304/128, 8192/128), 128, GEMM_SMEM>>>(
        xc_ptr, wqkvT_ptr, qkv_b, nullptr, 8192, 768, 2304, 1);
    // 2) fused attention -> g_att (tf32, c-permuted)
    attn_kernel<<<dim3(N_/128, H_, B_), 256, ATTN_SMEM>>>(alibi, pmask);
    // 3) output projection + bias -> d_out (fp32)
    gemm_tf32_kernel<<<dim3(768/128, 8192/128), 128, GEMM_SMEM>>>(
        att_ptr, wprojT_ptr, proj_b, out, 8192, 768, 768, 0);
}

// round 10
// speedup vs baseline: 1.8174x; 1.0787x over previous
#include <cuda_runtime.h>
#include <cstdint>

// Problem constants
#define B_  4
#define H_  12
#define N_  2048
#define D_  64
#define C_  768
#define BHND (B_*H_*N_*D_)

// Scratch (device globals — no allocation allowed)
__device__ float g_q[BHND];            // [b,h][n][d]  tf32, d-permuted
__device__ float g_k[BHND];            // [b,h][n][d]  tf32, d-permuted
__device__ float g_v[BHND];            // [b,h][d][n]  tf32, TRANSPOSED, keys NOT permuted
__device__ float g_att[B_*N_*C_];      // [b,n][c]     tf32, c-permuted
__device__ float g_xc[B_*N_*C_];       // x, tf32, k-permuted
__device__ float g_wqkvT[3*C_*C_];     // qkv_w transposed [2304][768], tf32, k-permuted
__device__ float g_wprojT[C_*C_];      // proj_w transposed [768][768], tf32, k-permuted

#define LOG2E 1.4426950408889634f

__device__ __forceinline__ float to_tf32(float x){
    uint32_t u = __float_as_uint(x);
    asm("cvt.rna.tf32.f32 %0, %0;" : "+r"(u));
    return __uint_as_float(u);
}
__device__ __forceinline__ float ex2(float x){
    float r;
    asm("ex2.approx.ftz.f32 %0, %1;" : "=f"(r) : "f"(x));
    return r;
}
__device__ __forceinline__ int perm8(int j){ return (j & ~7) + 2*(j&3) + ((j>>2)&1); }

__device__ __forceinline__ void cp_async16(float* smem_dst, const float* gsrc){
    uint32_t s = (uint32_t)__cvta_generic_to_shared(smem_dst);
    asm volatile("cp.async.cg.shared.global [%0], [%1], 16;\n" :: "r"(s), "l"(gsrc));
}
__device__ __forceinline__ void cp_commit(){ asm volatile("cp.async.commit_group;\n"); }
template<int NN>
__device__ __forceinline__ void cp_wait(){ asm volatile("cp.async.wait_group %0;\n" :: "n"(NN)); }

// D = A(16x8, row) * B(8x8, col) + D ; tf32 inputs, fp32 accum
__device__ __forceinline__ void mma8(float d[4], const float a[4], float b0, float b1){
    asm volatile(
        "mma.sync.aligned.m16n8k8.row.col.f32.tf32.tf32.f32 "
        "{%0,%1,%2,%3},{%4,%5,%6,%7},{%8,%9},{%0,%1,%2,%3};\n"
        : "+f"(d[0]), "+f"(d[1]), "+f"(d[2]), "+f"(d[3])
        : "r"(__float_as_uint(a[0])), "r"(__float_as_uint(a[1])),
          "r"(__float_as_uint(a[2])), "r"(__float_as_uint(a[3])),
          "r"(__float_as_uint(b0)),   "r"(__float_as_uint(b1)));
}

// ---------------------------------------------------------------------------
// Conversion kernels (one-time per launch)
// ---------------------------------------------------------------------------
__global__ void cvt_perm_rows(const float* __restrict__ in, float* __restrict__ out, int n8){
    int g = blockIdx.x*blockDim.x + threadIdx.x;
    if (g >= n8) return;
    const float4* p = (const float4*)(in + (size_t)g*8);
    float4 u = p[0], v = p[1];
    float vals[8] = {u.x,u.y,u.z,u.w,v.x,v.y,v.z,v.w};
    float* o = out + (size_t)g*8;
    #pragma unroll
    for (int j = 0; j < 8; j++) o[2*(j&3)+((j>>2)&1)] = to_tf32(vals[j]);
}
__global__ void cvt_perm_T(const float* __restrict__ w, float* __restrict__ wt, int K, int NO){
    int idx = blockIdx.x*blockDim.x + threadIdx.x;
    if (idx >= K*NO) return;
    int k = idx / NO, n = idx % NO;
    wt[(size_t)n*K + perm8(k)] = to_tf32(w[idx]);
}

// ---------------------------------------------------------------------------
// TF32 GEMM:  out = A[M,K] @ Wt[N,K]^T + bias   (A, Wt pre-tf32, k-permuted)
// 128 threads, 4 warps (2x2), warp tile 64x64, register-double-buffered frags.
// mode 0: row-major fp32 store; mode 1: QKV scatter (q,k d-perm; v transposed)
// ---------------------------------------------------------------------------
#define GSTR 40
#define GBUF (128*GSTR)   // 5120 floats per buffer

__global__ __launch_bounds__(128,2) void gemm_tf32_kernel(
    const float* __restrict__ A, const float* __restrict__ Wt,
    const float* __restrict__ bias, float* __restrict__ out,
    int M, int K, int NO, int mode)
{
    extern __shared__ float smem[];
    float* sA = smem;                 // [2][128*40]
    float* sB = smem + 2*GBUF;        // [2][128*40]

    const int tid  = threadIdx.x;
    const int lane = tid & 31;
    const int warp = tid >> 5;        // 0..3
    const int wm   = warp & 1;        // m offset wm*64
    const int wn   = warp >> 1;       // n offset wn*64
    const int m0   = blockIdx.y * 128;
    const int n0   = blockIdx.x * 128;
    const int R    = lane >> 2;
    const int t2   = (lane & 3) << 1;

    float acc[4][8][4];
    #pragma unroll
    for (int i = 0; i < 4; i++)
        #pragma unroll
        for (int j = 0; j < 8; j++)
            #pragma unroll
            for (int r = 0; r < 4; r++) acc[i][j][r] = 0.f;

    const int steps = K >> 5;

    auto load_step = [&](int k0, int buf){
        float* dA = sA + buf*GBUF;
        float* dB = sB + buf*GBUF;
        #pragma unroll
        for (int i = 0; i < 8; i++){
            int id  = tid + i*128;
            int row = id >> 3;
            int c4  = (id & 7) << 2;
            cp_async16(&dA[row*GSTR + c4], A  + (size_t)(m0 + row)*K + k0 + c4);
        }
        #pragma unroll
        for (int i = 0; i < 8; i++){
            int id  = tid + i*128;
            int row = id >> 3;
            int c4  = (id & 7) << 2;
            cp_async16(&dB[row*GSTR + c4], Wt + (size_t)(n0 + row)*K + k0 + c4);
        }
        cp_commit();
    };

    load_step(0, 0);
    load_step(32, 1);

    float af[2][4][4];
    float bf[2][8][2];

    for (int it = 0; it < steps; it++){
        if (it + 1 < steps) cp_wait<1>(); else cp_wait<0>();
        __syncthreads();

        const float* cA = sA + (it & 1)*GBUF;
        const float* cB = sB + (it & 1)*GBUF;

        // preload frags for kk = 0 into reg buffer 0
        #pragma unroll
        for (int mf = 0; mf < 4; mf++){
            int rbase = wm*64 + mf*16 + R;
            float2 p0 = *(const float2*)&cA[rbase*GSTR + t2];
            float2 p1 = *(const float2*)&cA[(rbase+8)*GSTR + t2];
            af[0][mf][0] = p0.x; af[0][mf][1] = p1.x; af[0][mf][2] = p0.y; af[0][mf][3] = p1.y;
        }
        #pragma unroll
        for (int nf = 0; nf < 8; nf++){
            float2 bp = *(const float2*)&cB[(wn*64 + nf*8 + R)*GSTR + t2];
            bf[0][nf][0] = bp.x; bf[0][nf][1] = bp.y;
        }

        #pragma unroll
        for (int kk = 0; kk < 4; kk++){
            const int cur = kk & 1;
            const int nxt = cur ^ 1;
            if (kk < 3){
                #pragma unroll
                for (int mf = 0; mf < 4; mf++){
                    int rbase = wm*64 + mf*16 + R;
                    float2 p0 = *(const float2*)&cA[rbase*GSTR + (kk+1)*8 + t2];
                    float2 p1 = *(const float2*)&cA[(rbase+8)*GSTR + (kk+1)*8 + t2];
                    af[nxt][mf][0] = p0.x; af[nxt][mf][1] = p1.x;
                    af[nxt][mf][2] = p0.y; af[nxt][mf][3] = p1.y;
                }
                #pragma unroll
                for (int nf = 0; nf < 8; nf++){
                    float2 bp = *(const float2*)&cB[(wn*64 + nf*8 + R)*GSTR + (kk+1)*8 + t2];
                    bf[nxt][nf][0] = bp.x; bf[nxt][nf][1] = bp.y;
                }
            }
            #pragma unroll
            for (int nf = 0; nf < 8; nf++)
                #pragma unroll
                for (int mf = 0; mf < 4; mf++)
                    mma8(acc[mf][nf], af[cur][mf], bf[cur][nf][0], bf[cur][nf][1]);
        }
        __syncthreads();
        if (it + 2 < steps) load_step((it+2) << 5, it & 1);
    }

    // epilogue
    #pragma unroll
    for (int mf = 0; mf < 4; mf++){
        #pragma unroll
        for (int nf = 0; nf < 8; nf++){
            #pragma unroll
            for (int rr = 0; rr < 2; rr++){
                int gm  = m0 + wm*64 + mf*16 + R + rr*8;
                int gn0 = n0 + wn*64 + nf*8 + t2;
                float v0 = acc[mf][nf][rr*2+0] + bias[gn0];
                float v1 = acc[mf][nf][rr*2+1] + bias[gn0+1];
                if (mode == 0){
                    *(float2*)(out + (size_t)gm*NO + gn0) = make_float2(v0, v1);
                } else {
                    int three = gn0 / 768;
                    int rem   = gn0 % 768;
                    int h     = rem / 64;
                    int d     = rem & 63;
                    int b     = gm >> 11;
                    int n     = gm & 2047;
                    size_t bh = (size_t)(b*H_ + h);
                    if (three == 0){
                        size_t ro = (bh*N_ + n)*D_;
                        g_q[ro + perm8(d)]   = to_tf32(v0);
                        g_q[ro + perm8(d+1)] = to_tf32(v1);
                    } else if (three == 1){
                        size_t ro = (bh*N_ + n)*D_;
                        g_k[ro + perm8(d)]   = to_tf32(v0);
                        g_k[ro + perm8(d+1)] = to_tf32(v1);
                    } else {  // v: transposed [d][n], keys NOT permuted
                        size_t vo = (bh*D_ + d)*N_ + n;
                        g_v[vo]      = to_tf32(v0);
                        g_v[vo + N_] = to_tf32(v1);
                    }
                }
            }
        }
    }
}

// ---------------------------------------------------------------------------
// Fused attention: 128 q-rows/CTA, 8 warps x 16 rows, key tile 64.
// PV consumes the S accumulator fragment DIRECTLY as mma A-operand: the
// contraction-index bijection mu(c)=2(c&3)+((c>>2)&1) is absorbed by loading
// V^T (unpermuted keys) at positions (2t, 2t+1). Zero shuffles.
// ---------------------------------------------------------------------------
#define KSTR 72
#define KV_BUF (64*KSTR)
#define ASTR 72
#define NEG_INF __int_as_float(0xff800000)

__global__ __launch_bounds__(256,2) void attn_kernel(
    const float* __restrict__ alibi, const int* __restrict__ pmask)
{
    extern __shared__ float sm[];
    float* KsB = sm;                   // [2][64*72]
    float* VsB = sm + 2*KV_BUF;        // [2][64*72]
    float* ALs = sm + 4*KV_BUF;        // [128*72] alibi stage (warp-private rows)

    const int tid  = threadIdx.x;
    const int lane = tid & 31;
    const int warp = tid >> 5;
    const int q0 = blockIdx.x * 128;
    const int h  = blockIdx.y;
    const int b  = blockIdx.z;
    const int R  = lane >> 2;
    const int t2 = (lane & 3) << 1;

    const int r0 = q0 + warp*16 + R;
    const size_t bh = (size_t)(b*H_ + h);
    const float* qp = g_q + bh*N_*D_;

    const float qscale = 0.125f * LOG2E;
    float qa[8][4];
    #pragma unroll
    for (int ks = 0; ks < 8; ks++){
        float2 p0 = *(const float2*)&qp[(size_t)r0*64 + ks*8 + t2];
        float2 p1 = *(const float2*)&qp[(size_t)(r0+8)*64 + ks*8 + t2];
        qa[ks][0] = to_tf32(p0.x*qscale); qa[ks][1] = to_tf32(p1.x*qscale);
        qa[ks][2] = to_tf32(p0.y*qscale); qa[ks][3] = to_tf32(p1.y*qscale);
    }

    float o[8][4];
    #pragma unroll
    for (int nf = 0; nf < 8; nf++){ o[nf][0]=o[nf][1]=o[nf][2]=o[nf][3]=0.f; }
    float mrun0 = -1e30f, mrun1 = -1e30f, l0 = 0.f, l1 = 0.f;

    const float* kbase = g_k + bh*N_*D_;            // [key][d]
    const float* vbase = g_v + bh*(size_t)D_*N_;    // [d][key]
    const float* abase = alibi + (bh*N_ + q0 + warp*16)*(size_t)N_;
    const int* pm = pmask + b*N_;

    auto load_kv = [&](int j0, int buf){
        float* dK = KsB + buf*KV_BUF;
        float* dV = VsB + buf*KV_BUF;
        #pragma unroll
        for (int i = 0; i < 4; i++){
            int id  = tid + i*256;
            int row = id >> 4;
            int c4  = (id & 15) << 2;
            cp_async16(&dK[row*KSTR + c4], kbase + (size_t)(j0+row)*64 + c4);
            cp_async16(&dV[row*KSTR + c4], vbase + (size_t)row*N_ + j0 + c4);
        }
        cp_commit();
    };
    auto load_al = [&](int j0){
        #pragma unroll
        for (int i = 0; i < 8; i++){
            int id = i*32 + lane;
            int rr = id >> 4;
            int cc = (id & 15) << 2;
            cp_async16(&ALs[(warp*16 + rr)*ASTR + cc],
                       abase + (size_t)rr*N_ + j0 + cc);
        }
        cp_commit();
    };

    load_kv(0, 0);
    load_kv(64, 1);
    load_al(0);

    unsigned mlo = __ballot_sync(0xffffffffu, pm[lane]      != 0);
    unsigned mhi = __ballot_sync(0xffffffffu, pm[32 + lane] != 0);

    for (int it = 0; it < 32; it++){
        const int j0 = it << 6;
        if (it == 0 || it == 31) cp_wait<0>(); else cp_wait<1>();
        __syncthreads();

        const float* Ks = KsB + (it & 1)*KV_BUF;
        const float* Vs = VsB + (it & 1)*KV_BUF;

        // S init = alibi * log2e
        float s[8][4];
        #pragma unroll
        for (int nf = 0; nf < 8; nf++){
            int c = nf*8 + t2;
            float2 a0 = *(const float2*)&ALs[(warp*16 + R)*ASTR + c];
            float2 a1 = *(const float2*)&ALs[(warp*16 + R + 8)*ASTR + c];
            s[nf][0] = a0.x*LOG2E; s[nf][1] = a0.y*LOG2E;
            s[nf][2] = a1.x*LOG2E; s[nf][3] = a1.y*LOG2E;
        }

        // S += Q' @ K^T
        #pragma unroll
        for (int ks = 0; ks < 8; ks++){
            #pragma unroll
            for (int nf = 0; nf < 8; nf++){
                float2 bp = *(const float2*)&Ks[(nf*8 + R)*KSTR + ks*8 + t2];
                mma8(s[nf], qa[ks], bp.x, bp.y);
            }
        }

        __syncwarp();
        if (it + 1 < 32) load_al(j0 + 64);

        unsigned nlo = 0, nhi = 0;
        if (it + 1 < 32){
            nlo = __ballot_sync(0xffffffffu, pm[j0 + 64 + lane] != 0);
            nhi = __ballot_sync(0xffffffffu, pm[j0 + 96 + lane] != 0);
        }

        // padding mask (S cols map to keys identically)
        #pragma unroll
        for (int nf = 0; nf < 8; nf++){
            int c = nf*8 + t2;
            unsigned bit0 = ((c   < 32) ? (mlo >> c)      : (mhi >> (c-32)))   & 1u;
            unsigned bit1 = ((c+1 < 32) ? (mlo >> (c+1))  : (mhi >> (c+1-32))) & 1u;
            if (bit0){ s[nf][0] = NEG_INF; s[nf][2] = NEG_INF; }
            if (bit1){ s[nf][1] = NEG_INF; s[nf][3] = NEG_INF; }
        }

        // online softmax in log2 domain
        float mx0 = -INFINITY, mx1 = -INFINITY;
        #pragma unroll
        for (int nf = 0; nf < 8; nf++){
            mx0 = fmaxf(mx0, fmaxf(s[nf][0], s[nf][1]));
            mx1 = fmaxf(mx1, fmaxf(s[nf][2], s[nf][3]));
        }
        mx0 = fmaxf(mx0, __shfl_xor_sync(0xffffffffu, mx0, 1));
        mx0 = fmaxf(mx0, __shfl_xor_sync(0xffffffffu, mx0, 2));
        mx1 = fmaxf(mx1, __shfl_xor_sync(0xffffffffu, mx1, 1));
        mx1 = fmaxf(mx1, __shfl_xor_sync(0xffffffffu, mx1, 2));
        float mn0 = fmaxf(mrun0, mx0);
        float mn1 = fmaxf(mrun1, mx1);
        float al0 = ex2(mrun0 - mn0);
        float al1 = ex2(mrun1 - mn1);
        mrun0 = mn0; mrun1 = mn1;

        float ls0 = 0.f, ls1 = 0.f;
        #pragma unroll
        for (int nf = 0; nf < 8; nf++){
            s[nf][0] = ex2(s[nf][0] - mn0); ls0 += s[nf][0];
            s[nf][1] = ex2(s[nf][1] - mn0); ls0 += s[nf][1];
            s[nf][2] = ex2(s[nf][2] - mn1); ls1 += s[nf][2];
            s[nf][3] = ex2(s[nf][3] - mn1); ls1 += s[nf][3];
            o[nf][0] *= al0; o[nf][1] *= al0; o[nf][2] *= al1; o[nf][3] *= al1;
        }
        ls0 += __shfl_xor_sync(0xffffffffu, ls0, 1);
        ls0 += __shfl_xor_sync(0xffffffffu, ls0, 2);
        ls1 += __shfl_xor_sync(0xffffffffu, ls1, 1);
        ls1 += __shfl_xor_sync(0xffffffffu, ls1, 2);
        l0 = l0*al0 + ls0;
        l1 = l1*al1 + ls1;

        // O += P @ V : S fragment used directly as A (mu-bijection absorbed by
        // loading V^T at key positions (2t, 2t+1)). Zero shuffles.
        #pragma unroll
        for (int ks = 0; ks < 8; ks++){
            float pa[4];
            pa[0] = to_tf32(s[ks][0]);
            pa[1] = to_tf32(s[ks][2]);
            pa[2] = to_tf32(s[ks][1]);
            pa[3] = to_tf32(s[ks][3]);
            #pragma unroll
            for (int nf = 0; nf < 8; nf++){
                float2 bp = *(const float2*)&Vs[(nf*8 + R)*KSTR + ks*8 + t2];
                mma8(o[nf], pa, bp.x, bp.y);
            }
        }
        __syncthreads();
        if (it + 2 < 32) load_kv((it+2) << 6, it & 1);
        mlo = nlo; mhi = nhi;
    }

    // epilogue: normalized O -> g_att as tf32, column-permuted
    const float inv0 = 1.0f / l0;
    const float inv1 = 1.0f / l1;
    float* orow0 = g_att + ((size_t)(b*N_ + r0))*C_;
    float* orow1 = orow0 + (size_t)8*C_;
    #pragma unroll
    for (int nf = 0; nf < 8; nf++){
        int c = h*64 + nf*8 + t2;
        orow0[perm8(c)]   = to_tf32(o[nf][0]*inv0);
        orow0[perm8(c+1)] = to_tf32(o[nf][1]*inv0);
        orow1[perm8(c)]   = to_tf32(o[nf][2]*inv1);
        orow1[perm8(c+1)] = to_tf32(o[nf][3]*inv1);
    }
}

// ---------------------------------------------------------------------------
extern "C" void kernel_launch(void* const* d_in, const int* in_sizes, int n_in,
                              void* d_out, int out_size)
{
    (void)in_sizes; (void)n_in; (void)out_size;
    const float* x      = (const float*)d_in[0];
    const int*   pmask  = (const int*)d_in[1];
    const float* alibi  = (const float*)d_in[2];
    const float* qkv_w  = (const float*)d_in[3];
    const float* qkv_b  = (const float*)d_in[4];
    const float* proj_w = (const float*)d_in[5];
    const float* proj_b = (const float*)d_in[6];
    float*       out    = (float*)d_out;

    const int GEMM_SMEM = (4*GBUF) * 4;                       // 81920 B
    const int ATTN_SMEM = (4*KV_BUF + 128*ASTR) * 4;          // 110592 B
    cudaFuncSetAttribute(gemm_tf32_kernel, cudaFuncAttributeMaxDynamicSharedMemorySize, GEMM_SMEM);
    cudaFuncSetAttribute(attn_kernel, cudaFuncAttributeMaxDynamicSharedMemorySize, ATTN_SMEM);

    float *att_ptr = nullptr, *xc_ptr = nullptr, *wqkvT_ptr = nullptr, *wprojT_ptr = nullptr;
    cudaGetSymbolAddress((void**)&att_ptr,    g_att);
    cudaGetSymbolAddress((void**)&xc_ptr,     g_xc);
    cudaGetSymbolAddress((void**)&wqkvT_ptr,  g_wqkvT);
    cudaGetSymbolAddress((void**)&wprojT_ptr, g_wprojT);

    // 0) one-time conversions: tf32 + contraction-dim permutation
    {
        int n8 = (B_*N_*C_) / 8;
        cvt_perm_rows<<<(n8 + 255)/256, 256>>>(x, xc_ptr, n8);
        int nq = C_ * 3*C_;
        cvt_perm_T<<<(nq + 255)/256, 256>>>(qkv_w, wqkvT_ptr, C_, 3*C_);
        int np = C_ * C_;
        cvt_perm_T<<<(np + 255)/256, 256>>>(proj_w, wprojT_ptr, C_, C_);
    }
    // 1) QKV projection + bias + scatter (q,k d-perm; v transposed, unpermuted)
    gemm_tf32_kernel<<<dim3(2304/128, 8192/128), 128, GEMM_SMEM>>>(
        xc_ptr, wqkvT_ptr, qkv_b, nullptr, 8192, 768, 2304, 1);
    // 2) fused attention -> g_att (tf32, c-permuted)
    attn_kernel<<<dim3(N_/128, H_, B_), 256, ATTN_SMEM>>>(alibi, pmask);
    // 3) output projection + bias -> d_out (fp32)
    gemm_tf32_kernel<<<dim3(768/128, 8192/128), 128, GEMM_SMEM>>>(
        att_ptr, wprojT_ptr, proj_b, out, 8192, 768, 768, 0);
}